// round 11
// baseline (speedup 1.0000x reference)
#include <cuda_runtime.h>
#include <cuda_fp16.h>
#include <cstdint>

#define B_ 8
#define C_ 256
#define N_ 4096
#define K_ 64
#define MT 32
#define NB 64                            // q-rows per CTA
#define NT2 64                           // m-tiles per warp-group (128 total / 2)
#define LOG2E 1.4426950408889634f

// Scratch (fp16 hi/lo packed), PERMUTED for wide LDS fragment loads.
// F/G row (per n): 32 k-pairs in 4 blocks of 8; within a block, pair qb is
// stored at position perm(qb) = (qb&3)*2 + (qb>>2); each position = (hi,lo).
// H: fp16 single, transposed [b][d][m-pairs], same per-8-block permutation.
__device__ uint32_t g_F[(size_t)B_ * N_ * 64];
__device__ uint32_t g_G[(size_t)B_ * N_ * 64];     // pre-scaled by log2(e)
__device__ uint16_t g_H[(size_t)B_ * C_ * N_];

// ---------------- helpers ----------------
__device__ __forceinline__ uint32_t f16x2(float lo, float hi) {
    uint32_t r;
    asm("cvt.rn.f16x2.f32 %0, %1, %2;" : "=r"(r) : "f"(hi), "f"(lo));
    return r;
}
__device__ __forceinline__ float f16lo(uint32_t p) {
    return __half2float(__ushort_as_half((unsigned short)(p & 0xffffu)));
}
__device__ __forceinline__ float f16hi(uint32_t p) {
    return __half2float(__ushort_as_half((unsigned short)(p >> 16)));
}
__device__ __forceinline__ float ex2(float x) {
    float r; asm("ex2.approx.f32 %0, %1;" : "=f"(r) : "f"(x)); return r;
}
__device__ __forceinline__ void mma_f16(float* c,
    uint32_t a0, uint32_t a1, uint32_t a2, uint32_t a3,
    uint32_t b0, uint32_t b1) {
    asm volatile("mma.sync.aligned.m16n8k16.row.col.f32.f16.f16.f32 "
        "{%0,%1,%2,%3},{%4,%5,%6,%7},{%8,%9},{%0,%1,%2,%3};"
        : "+f"(c[0]), "+f"(c[1]), "+f"(c[2]), "+f"(c[3])
        : "r"(a0), "r"(a1), "r"(a2), "r"(a3), "r"(b0), "r"(b1));
}
__device__ __forceinline__ void cp16(uint32_t dst, const void* src) {
    asm volatile("cp.async.cg.shared.global [%0], [%1], 16;" :: "r"(dst), "l"(src));
}
__device__ __forceinline__ void cp_commit() { asm volatile("cp.async.commit_group;"); }
__device__ __forceinline__ void cp_wait0()  { asm volatile("cp.async.wait_group 0;"); }
__device__ __forceinline__ void group_bar(int id) {
    asm volatile("bar.sync %0, 128;" :: "r"(id) : "memory");
}
__device__ __forceinline__ unsigned long long ffma2(unsigned long long a,
                                                    unsigned long long b,
                                                    unsigned long long c) {
    unsigned long long d;
    asm("fma.rn.f32x2 %0, %1, %2, %3;" : "=l"(d) : "l"(a), "l"(b), "l"(c));
    return d;
}
__device__ __forceinline__ unsigned long long pack2(float x) {
    unsigned long long r;
    unsigned int xi = __float_as_uint(x);
    asm("mov.b64 %0, {%1, %1};" : "=l"(r) : "r"(xi));
    return r;
}
__device__ __forceinline__ unsigned long long pack2v(float a, float b) {
    unsigned long long r;
    asm("mov.b64 %0, {%1, %2};" : "=l"(r)
        : "r"(__float_as_uint(a)), "r"(__float_as_uint(b)));
    return r;
}
__device__ __forceinline__ float2 unpack2(unsigned long long v) {
    unsigned int lo, hi;
    asm("mov.b64 {%0, %1}, %2;" : "=r"(lo), "=r"(hi) : "l"(v));
    return make_float2(__uint_as_float(lo), __uint_as_float(hi));
}

// ---------------------------------------------------------------------------
// Projection (unchanged from round 8): thread computes 8 rows x 4 n,
// stores to the permuted fp16 hi/lo layouts.
// ---------------------------------------------------------------------------
__global__ __launch_bounds__(128) void proj_kernel(
    const float* __restrict__ feat,
    const float* __restrict__ WF,
    const float* __restrict__ WG,
    const float* __restrict__ WH)
{
    __shared__ float sW[256 * 36];
    const int rg = blockIdx.y;
    const int b  = blockIdx.z;

    const float* W;
    int r0, mode;                      // 0=F, 1=G, 2=H
    if (rg < 2)      { W = WF; r0 = rg * 32;       mode = 0; }
    else if (rg < 4) { W = WG; r0 = (rg - 2) * 32; mode = 1; }
    else             { W = WH; r0 = (rg - 4) * 32; mode = 2; }

    for (int i = threadIdx.x; i < 32 * 256; i += 128) {
        int r = i >> 8, c = i & 255;
        sW[c * 36 + r] = W[(size_t)(r0 + r) * C_ + c];
    }
    __syncthreads();

    const int q  = threadIdx.x & 31;
    const int rh = threadIdx.x >> 5;
    const int n  = blockIdx.x * 128 + q * 4;
    const float* fb = feat + (size_t)b * C_ * N_;
    const float* wp = sW + rh * 8;

    unsigned long long acc[8][2];
#pragma unroll
    for (int j = 0; j < 8; j++) { acc[j][0] = 0ULL; acc[j][1] = 0ULL; }

#pragma unroll 4
    for (int c = 0; c < C_; c++) {
        float4 x = __ldg((const float4*)(fb + (size_t)c * N_ + n));
        unsigned long long x01 = pack2v(x.x, x.y);
        unsigned long long x23 = pack2v(x.z, x.w);
        float4 w0 = *(const float4*)(wp + c * 36);
        float4 w1 = *(const float4*)(wp + c * 36 + 4);
#pragma unroll
        for (int j = 0; j < 8; j++) {
            float wj = (j < 4) ? ((const float*)&w0)[j] : ((const float*)&w1)[j - 4];
            unsigned long long w2 = pack2(wj);
            acc[j][0] = ffma2(x01, w2, acc[j][0]);
            acc[j][1] = ffma2(x23, w2, acc[j][1]);
        }
    }

    float val[8][4];
#pragma unroll
    for (int j = 0; j < 8; j++) {
        float2 a = unpack2(acc[j][0]);
        float2 c2 = unpack2(acc[j][1]);
        val[j][0] = a.x; val[j][1] = a.y; val[j][2] = c2.x; val[j][3] = c2.y;
    }

    if (mode == 2) {
        const int P0 = n >> 1;
        const int base = P0 & ~15;
        const int pt = P0 & 15;
        const int jj = pt >> 3;
        const int qb = pt & 7;
        const int pos = base + jj * 8 + (qb & 3) * 2 + (qb >> 2);
#pragma unroll
        for (int j = 0; j < 8; j++) {
            const int d = r0 + rh * 8 + j;
            uint32_t* dst = (uint32_t*)g_H + ((size_t)b * C_ + d) * 2048;
            dst[pos]     = f16x2(val[j][0], val[j][1]);
            dst[pos + 2] = f16x2(val[j][2], val[j][3]);
        }
    } else {
        const float scale = (mode == 1) ? LOG2E : 1.0f;
        uint32_t* dstb = (mode == 1 ? g_G : g_F);
        const int p0  = (r0 + rh * 8) >> 1;
        const int blk = p0 >> 3;
        const int qb0 = p0 & 7;
#pragma unroll
        for (int e = 0; e < 4; e++) {
            uint32_t* dst = dstb + ((size_t)b * N_ + n + e) * 64 + blk * 16;
#pragma unroll
            for (int jp = 0; jp < 4; jp++) {
                const int qb = qb0 + jp;
                const int pos = ((qb & 3) * 2 + (qb >> 2)) * 2;
                float x0 = val[2 * jp][e] * scale;
                float x1 = val[2 * jp + 1][e] * scale;
                uint32_t hi2 = f16x2(x0, x1);
                uint32_t lo2 = f16x2(x0 - f16lo(hi2), x1 - f16hi(hi2));
                uint2 o; o.x = hi2; o.y = lo2;
                *(uint2*)(dst + pos) = o;
            }
        }
    }
}

// ---------------------------------------------------------------------------
// Split-K(m) flash attention. CTA = 64 q-rows, 8 warps in TWO groups of 4.
// Group g handles m-tiles [g*64, g*64+64), own F/H double buffers, own named
// barrier -> groups progress independently (one warp of each per SMSP).
// Per-warp math identical to round 8 (permuted layouts, LDS.128/LDS.64 frags,
// S 3-pass fp16 k16, PV 1-pass fp16). Final split-K merge via smem.
// ---------------------------------------------------------------------------
#define GROW 80
#define HROW 24
#define SG  0                            // 64 * 80 = 5120 u32
#define SF  (NB * GROW)                  // F planes [g*2+buf], 4 x FPL
#define FPL (MT * GROW)                  // 2560
#define SH  (SF + 4 * FPL)               // H planes [g*2+buf], 4 x HPL
#define HPL (C_ * HROW)                  // 6144
#define SMEMU (SH + 4 * HPL)             // 39936 u32
#define SMEMB (SMEMU * 4)                // 159744 B

__global__ __launch_bounds__(256, 1) void attn_kernel(
    const float* __restrict__ input,
    const float* __restrict__ gamma_p,
    float* __restrict__ out)
{
    extern __shared__ uint32_t sm[];
    uint32_t smu;
    asm("{ .reg .u64 t; cvta.to.shared.u64 t, %1; cvt.u32.u64 %0, t; }"
        : "=r"(smu) : "l"(sm));

    const int tid  = threadIdx.x;
    const int lane = tid & 31;
    const int w    = tid >> 5;       // warp 0..7
    const int g    = w >> 2;         // group 0/1
    const int wg   = w & 3;          // warp in group; owns rows [16wg,16wg+16)
    const int t2   = wg * 32 + lane; // thread index within group [0,128)
    const int gr   = lane >> 2;
    const int tg   = lane & 3;
    const int n0   = blockIdx.x * NB;
    const int b    = blockIdx.y;

    const uint32_t* FG = g_F + (size_t)b * N_ * 64;
    const uint32_t* HG = (const uint32_t*)(g_H + (size_t)b * C_ * N_);

    // stage G tile (64 rows x 64 u32) cooperatively (all 256 threads)
    {
        const uint32_t* GG = g_G + ((size_t)b * N_ + n0) * 64;
        for (int i = tid; i < NB * 16; i += 256) {
            int r = i >> 4, ch = i & 15;
            cp16(smu + (SG + r * GROW + ch * 4) * 4, GG + r * 64 + ch * 4);
        }
    }
    // each group prefetches ITS m-tile 0 into its buf 0
    {
        const int m0 = g * NT2 * MT;
        const int fpl = (g * 2) * FPL, hpl = (g * 2) * HPL;
        for (int i = t2; i < 512; i += 128) {
            int r = i >> 4, ch = i & 15;
            cp16(smu + (SF + fpl + r * GROW + ch * 4) * 4,
                 FG + (size_t)(m0 + r) * 64 + ch * 4);
        }
        for (int i = t2; i < 1024; i += 128) {
            int r = i >> 2, ch = i & 3;
            cp16(smu + (SH + hpl + r * HROW + ch * 4) * 4,
                 HG + (size_t)r * 2048 + m0 / 2 + ch * 4);
        }
        cp_commit();
    }

    float oacc[32][4];
#pragma unroll
    for (int i = 0; i < 32; i++) {
        oacc[i][0] = 0.f; oacc[i][1] = 0.f; oacc[i][2] = 0.f; oacc[i][3] = 0.f;
    }
    const float NEG_INF = __int_as_float(0xff800000);
    float mrow0 = NEG_INF, mrow1 = NEG_INF, lsum0 = 0.f, lsum1 = 0.f;

    const uint32_t* g0 = sm + SG + (wg * 16 + gr) * GROW;

#pragma unroll 1
    for (int tt = 0; tt < NT2; tt++) {
        cp_wait0();
        if (tt == 0) __syncthreads();        // G visibility across groups
        else        group_bar(1 + g);        // group-private pipeline barrier

        const int cur = tt & 1;
        if (tt + 1 < NT2) {
            const int m0n = (g * NT2 + tt + 1) * MT;
            const int nb = cur ^ 1;
            const int fpl = (g * 2 + nb) * FPL, hpl = (g * 2 + nb) * HPL;
            for (int i = t2; i < 512; i += 128) {
                int r = i >> 4, ch = i & 15;
                cp16(smu + (SF + fpl + r * GROW + ch * 4) * 4,
                     FG + (size_t)(m0n + r) * 64 + ch * 4);
            }
            for (int i = t2; i < 1024; i += 128) {
                int r = i >> 2, ch = i & 3;
                cp16(smu + (SH + hpl + r * HROW + ch * 4) * 4,
                     HG + (size_t)r * 2048 + m0n / 2 + ch * 4);
            }
            cp_commit();
        }

        const uint32_t* sFc = sm + SF + (g * 2 + cur) * FPL;
        const uint32_t* sHc = sm + SH + (g * 2 + cur) * HPL;

        // ---- S tile: 3-pass fp16 k16; frags via LDS.128 (permuted) ----
        float sc[4][4];
#pragma unroll
        for (int ms = 0; ms < 4; ms++) {
            sc[ms][0] = 0.f; sc[ms][1] = 0.f; sc[ms][2] = 0.f; sc[ms][3] = 0.f;
        }
#pragma unroll
        for (int kc = 0; kc < 4; kc++) {
            const uint32_t* ga = g0 + kc * 16 + 4 * tg;
            uint4 Aa = *(const uint4*)ga;               // A0h,A0l,A2h,A2l
            uint4 Ab = *(const uint4*)(ga + 8 * GROW);  // A1h,A1l,A3h,A3l
#pragma unroll
            for (int ms = 0; ms < 4; ms++) {
                const uint32_t* f = sFc + (ms * 8 + gr) * GROW + kc * 16 + 4 * tg;
                uint4 Bv = *(const uint4*)f;            // B0h,B0l,B1h,B1l
                mma_f16(sc[ms], Aa.x, Ab.x, Aa.z, Ab.z, Bv.x, Bv.z);
                mma_f16(sc[ms], Aa.x, Ab.x, Aa.z, Ab.z, Bv.y, Bv.w);
                mma_f16(sc[ms], Aa.y, Ab.y, Aa.w, Ab.w, Bv.x, Bv.z);
            }
        }

        // ---- online softmax (log2 domain), lazy O-rescale ----
        float t0 = NEG_INF, t1 = NEG_INF;
#pragma unroll
        for (int ms = 0; ms < 4; ms++) {
            t0 = fmaxf(t0, fmaxf(sc[ms][0], sc[ms][1]));
            t1 = fmaxf(t1, fmaxf(sc[ms][2], sc[ms][3]));
        }
        t0 = fmaxf(t0, __shfl_xor_sync(0xffffffffu, t0, 1));
        t0 = fmaxf(t0, __shfl_xor_sync(0xffffffffu, t0, 2));
        t1 = fmaxf(t1, __shfl_xor_sync(0xffffffffu, t1, 1));
        t1 = fmaxf(t1, __shfl_xor_sync(0xffffffffu, t1, 2));

        const float mn0 = fmaxf(mrow0, t0);
        const float mn1 = fmaxf(mrow1, t1);
        const bool up = (mn0 != mrow0) || (mn1 != mrow1);
        if (__any_sync(0xffffffffu, up)) {
            const float cr0 = ex2(mrow0 - mn0);
            const float cr1 = ex2(mrow1 - mn1);
            lsum0 *= cr0; lsum1 *= cr1;
#pragma unroll
            for (int dt = 0; dt < 32; dt++) {
                oacc[dt][0] *= cr0; oacc[dt][1] *= cr0;
                oacc[dt][2] *= cr1; oacc[dt][3] *= cr1;
            }
            mrow0 = mn0; mrow1 = mn1;
        }
#pragma unroll
        for (int ms = 0; ms < 4; ms++) {
            sc[ms][0] = ex2(sc[ms][0] - mrow0);
            sc[ms][1] = ex2(sc[ms][1] - mrow0);
            sc[ms][2] = ex2(sc[ms][2] - mrow1);
            sc[ms][3] = ex2(sc[ms][3] - mrow1);
            lsum0 += sc[ms][0] + sc[ms][1];
            lsum1 += sc[ms][2] + sc[ms][3];
        }

        // ---- PV: O += P * H, 1-pass fp16; B-frags via LDS.64 (permuted) ----
#pragma unroll
        for (int j = 0; j < 2; j++) {
            const float* cA = sc[2 * j];
            const float* cB = sc[2 * j + 1];
            uint32_t p0 = f16x2(cA[0], cA[1]);
            uint32_t p1 = f16x2(cA[2], cA[3]);
            uint32_t p2 = f16x2(cB[0], cB[1]);
            uint32_t p3 = f16x2(cB[2], cB[3]);
            const uint32_t* hb = sHc + gr * HROW + j * 8 + 2 * tg;
#pragma unroll
            for (int dt = 0; dt < 32; dt++) {
                uint2 bv = *(const uint2*)(hb + dt * 8 * HROW);
                mma_f16(oacc[dt], p0, p1, p2, p3, bv.x, bv.y);
            }
        }
    }

    // ---- per-group l reduce across tg ----
    lsum0 += __shfl_xor_sync(0xffffffffu, lsum0, 1);
    lsum0 += __shfl_xor_sync(0xffffffffu, lsum0, 2);
    lsum1 += __shfl_xor_sync(0xffffffffu, lsum1, 1);
    lsum1 += __shfl_xor_sync(0xffffffffu, lsum1, 2);

    // ---- split-K merge: group 1 ships (O, m, l) via smem; group 0 merges ----
    __syncthreads();                         // all buffers dead; smem reusable
    float* ex = (float*)sm;                  // 128 threads x 132 floats = 67.6KB
    if (g == 1) {
        float* p = ex + t2 * 132;
#pragma unroll
        for (int dt = 0; dt < 32; dt++) {
            float4 v;
            v.x = oacc[dt][0]; v.y = oacc[dt][1];
            v.z = oacc[dt][2]; v.w = oacc[dt][3];
            *(float4*)(p + dt * 4) = v;
        }
        p[128] = mrow0; p[129] = mrow1; p[130] = lsum0; p[131] = lsum1;
    }
    __syncthreads();
    if (g == 0) {
        const float* p = ex + t2 * 132;
        const float mb0 = p[128], mb1 = p[129];
        const float lb0 = p[130], lb1 = p[131];
        const float mm0 = fmaxf(mrow0, mb0);
        const float mm1 = fmaxf(mrow1, mb1);
        const float ca0 = ex2(mrow0 - mm0), cb0 = ex2(mb0 - mm0);
        const float ca1 = ex2(mrow1 - mm1), cb1 = ex2(mb1 - mm1);
        const float lt0 = lsum0 * ca0 + lb0 * cb0;
        const float lt1 = lsum1 * ca1 + lb1 * cb1;
        const float inv0 = 1.0f / lt0;
        const float inv1 = 1.0f / lt1;
        const float gm = __ldg(gamma_p);

        const int r0 = n0 + wg * 16 + gr;
        const int r1 = r0 + 8;
        const size_t base0 = ((size_t)b * N_ + r0) * C_ + tg * 2;
        const size_t base1 = ((size_t)b * N_ + r1) * C_ + tg * 2;
#pragma unroll
        for (int dt = 0; dt < 32; dt++) {
            float4 pb = *(const float4*)(p + dt * 4);
            float o0 = oacc[dt][0] * ca0 + pb.x * cb0;
            float o1 = oacc[dt][1] * ca0 + pb.y * cb0;
            float o2 = oacc[dt][2] * ca1 + pb.z * cb1;
            float o3 = oacc[dt][3] * ca1 + pb.w * cb1;
            float2 iv0 = *(const float2*)(input + base0 + dt * 8);
            float2 iv1 = *(const float2*)(input + base1 + dt * 8);
            float2 ov0, ov1;
            ov0.x = fmaf(gm, o0 * inv0, iv0.x);
            ov0.y = fmaf(gm, o1 * inv0, iv0.y);
            ov1.x = fmaf(gm, o2 * inv1, iv1.x);
            ov1.y = fmaf(gm, o3 * inv1, iv1.y);
            *(float2*)(out + base0 + dt * 8) = ov0;
            *(float2*)(out + base1 + dt * 8) = ov1;
        }
    }
}

// ---------------------------------------------------------------------------
extern "C" void kernel_launch(void* const* d_in, const int* in_sizes, int n_in,
                              void* d_out, int out_size) {
    (void)in_sizes; (void)n_in; (void)out_size;
    const float* input = (const float*)d_in[0];
    const float* feat  = (const float*)d_in[1];   // nms_feat
    const float* WF    = (const float*)d_in[2];
    const float* WG    = (const float*)d_in[3];
    const float* WH    = (const float*)d_in[4];
    const float* gamma = (const float*)d_in[5];
    float* out = (float*)d_out;

    cudaFuncSetAttribute(attn_kernel,
                         cudaFuncAttributeMaxDynamicSharedMemorySize, SMEMB);

    proj_kernel<<<dim3(N_ / 128, 12, B_), 128>>>(feat, WF, WG, WH);
    attn_kernel<<<dim3(N_ / NB, B_), 256, SMEMB>>>(input, gamma, out);
}

// round 13
// speedup vs baseline: 1.0241x; 1.0241x over previous
#include <cuda_runtime.h>
#include <cuda_fp16.h>
#include <cstdint>

#define B_ 8
#define C_ 256
#define N_ 4096
#define K_ 64
#define MT 32
#define LOG2E 1.4426950408889634f

// Scratch (fp16 hi/lo packed), PERMUTED for wide LDS fragment loads.
// F/G row (per n): 32 k-pairs in 4 blocks of 8; within a block, pair qb is
// stored at position perm(qb) = (qb&3)*2 + (qb>>2); each position = (hi,lo).
// H: fp16 single, transposed [b][d][m-pairs], same per-8-block permutation.
__device__ uint32_t g_F[(size_t)B_ * N_ * 64];
__device__ uint32_t g_G[(size_t)B_ * N_ * 64];     // pre-scaled by log2(e)
__device__ uint16_t g_H[(size_t)B_ * C_ * N_];

// ---------------- helpers ----------------
__device__ __forceinline__ uint32_t f16x2(float lo, float hi) {
    uint32_t r;
    asm("cvt.rn.f16x2.f32 %0, %1, %2;" : "=r"(r) : "f"(hi), "f"(lo));
    return r;
}
__device__ __forceinline__ float f16lo(uint32_t p) {
    return __half2float(__ushort_as_half((unsigned short)(p & 0xffffu)));
}
__device__ __forceinline__ float f16hi(uint32_t p) {
    return __half2float(__ushort_as_half((unsigned short)(p >> 16)));
}
__device__ __forceinline__ float ex2(float x) {
    float r; asm("ex2.approx.f32 %0, %1;" : "=f"(r) : "f"(x)); return r;
}
__device__ __forceinline__ void mma_f16(float* c,
    uint32_t a0, uint32_t a1, uint32_t a2, uint32_t a3,
    uint32_t b0, uint32_t b1) {
    asm volatile("mma.sync.aligned.m16n8k16.row.col.f32.f16.f16.f32 "
        "{%0,%1,%2,%3},{%4,%5,%6,%7},{%8,%9},{%0,%1,%2,%3};"
        : "+f"(c[0]), "+f"(c[1]), "+f"(c[2]), "+f"(c[3])
        : "r"(a0), "r"(a1), "r"(a2), "r"(a3), "r"(b0), "r"(b1));
}
__device__ __forceinline__ void cp16(uint32_t dst, const void* src) {
    asm volatile("cp.async.cg.shared.global [%0], [%1], 16;" :: "r"(dst), "l"(src));
}
__device__ __forceinline__ void cp_commit() { asm volatile("cp.async.commit_group;"); }
__device__ __forceinline__ void cp_wait0()  { asm volatile("cp.async.wait_group 0;"); }

// pair permutation within an 8-pair block: u32 offset of pair p inside a
// 64-u32 row (4 blocks of 16 u32; each pair = (hi,lo) adjacent)
__device__ __forceinline__ int pair_off(int p) {
    int qb = p & 7;
    return (p >> 3) * 16 + ((qb & 3) * 2 + (qb >> 2)) * 2;
}

// ---------------------------------------------------------------------------
// Tensor-core projection. Block = 256 thr (8 warps), grid (32, 3, B).
//  rg=0 : FG mode — A = feat rows (128 n), B = [WF;WG] rows (128 r)
//  rg=1,2: H mode — A = WH rows (128 d),  B = feat rows (128 n)
// Operands staged per 64-c k-tile as fp16 hi/lo in the permuted row format;
// inner loop = round-8 S-loop (3-pass hi/lo, uint4 frags). Epilogues write
// the exact permuted g_F/g_G/g_H layouts the attention kernel consumes.
// ---------------------------------------------------------------------------
#define PGROW 80
#define PSMEMB (2 * 128 * PGROW * 4)     // 81920 B

__global__ __launch_bounds__(256) void proj_kernel(
    const float* __restrict__ feat,
    const float* __restrict__ WF,
    const float* __restrict__ WG,
    const float* __restrict__ WH)
{
    extern __shared__ uint32_t psm[];
    uint32_t* sA = psm;                  // A rows (n for FG, d for H)
    uint32_t* sB = psm + 128 * PGROW;    // B rows (r for FG, n for H)

    const int tid  = threadIdx.x;
    const int lane = tid & 31;
    const int w    = tid >> 5;
    const int gr   = lane >> 2;
    const int tg   = lane & 3;
    const int nb0  = blockIdx.x * 128;
    const int rg   = blockIdx.y;
    const int b    = blockIdx.z;
    const bool modeH = (rg > 0);
    const float* fb = feat + (size_t)b * C_ * N_;

    float acc[16][4];
#pragma unroll
    for (int i = 0; i < 16; i++) {
        acc[i][0] = 0.f; acc[i][1] = 0.f; acc[i][2] = 0.f; acc[i][3] = 0.f;
    }

#pragma unroll 1
    for (int kt = 0; kt < 4; kt++) {
        const int c0 = kt * 64;
        __syncthreads();

        // ---- stage feat tile (128 n x 64 c) -> sA (FG) or sB (H) ----
        {
            uint32_t* dst = modeH ? sB : sA;
            const int n_i  = tid & 127;
            const int half = tid >> 7;                 // c-half 0/1
            uint32_t* row = dst + n_i * PGROW;
            const float* fp = fb + (size_t)(c0 + half * 32) * N_ + nb0 + n_i;
#pragma unroll
            for (int p = 0; p < 16; p++) {
                float x0 = fp[(size_t)(2 * p) * N_];       // coalesced over n_i
                float x1 = fp[(size_t)(2 * p + 1) * N_];
                uint32_t hi2 = f16x2(x0, x1);
                uint32_t lo2 = f16x2(x0 - f16lo(hi2), x1 - f16hi(hi2));
                uint2 o; o.x = hi2; o.y = lo2;
                *(uint2*)(row + pair_off(half * 16 + p)) = o;
            }
        }
        // ---- stage W tile (128 rows x 64 c) -> sB (FG) or sA (H) ----
        {
            uint32_t* dst = modeH ? sA : sB;
            const int r    = tid >> 1;
            const int half = tid & 1;
            const float* Wr;
            if (modeH) Wr = WH + (size_t)((rg - 1) * 128 + r) * C_;
            else       Wr = (r < 64) ? WF + (size_t)r * C_
                                     : WG + (size_t)(r - 64) * C_;
            uint32_t* row = dst + r * PGROW;
            const float* wp = Wr + c0 + half * 32;
#pragma unroll
            for (int p = 0; p < 16; p++) {
                float2 x = *(const float2*)(wp + 2 * p);
                uint32_t hi2 = f16x2(x.x, x.y);
                uint32_t lo2 = f16x2(x.x - f16lo(hi2), x.y - f16hi(hi2));
                uint2 o; o.x = hi2; o.y = lo2;
                *(uint2*)(row + pair_off(half * 16 + p)) = o;
            }
        }
        __syncthreads();

        // ---- MMA: 3-pass hi/lo, A row = w*16+gr (+8), B rows t8*8+gr ----
        const uint32_t* ga = sA + (w * 16 + gr) * PGROW;
#pragma unroll
        for (int kc = 0; kc < 4; kc++) {
            const int o0 = kc * 16 + 4 * tg;
            uint4 Aa = *(const uint4*)(ga + o0);             // A0h,A0l,A2h,A2l
            uint4 Ab = *(const uint4*)(ga + 8 * PGROW + o0); // A1h,A1l,A3h,A3l
#pragma unroll
            for (int t8 = 0; t8 < 16; t8++) {
                const uint32_t* f = sB + (t8 * 8 + gr) * PGROW + o0;
                uint4 Bv = *(const uint4*)f;                 // B0h,B0l,B1h,B1l
                mma_f16(acc[t8], Aa.x, Ab.x, Aa.z, Ab.z, Bv.x, Bv.z);
                mma_f16(acc[t8], Aa.x, Ab.x, Aa.z, Ab.z, Bv.y, Bv.w);
                mma_f16(acc[t8], Aa.y, Ab.y, Aa.w, Ab.w, Bv.x, Bv.z);
            }
        }
    }

    // ---- epilogue ----
    if (!modeH) {
        // C frag: rows n = nb0+w*16+gr (+8); cols r = t8*8 + 2tg, 2tg+1
        const int n_row0 = nb0 + w * 16 + gr;
#pragma unroll
        for (int rt = 0; rt < 16; rt++) {
            const bool isG = (rt >= 8);
            const float scale = isG ? LOG2E : 1.0f;
            uint32_t* dstb = isG ? g_G : g_F;
            const int p = (isG ? rt - 8 : rt) * 4 + tg;      // k-pair index
            const int off = pair_off(p);
#pragma unroll
            for (int h = 0; h < 2; h++) {
                float v0 = acc[rt][2 * h] * scale;
                float v1 = acc[rt][2 * h + 1] * scale;
                uint32_t hi2 = f16x2(v0, v1);
                uint32_t lo2 = f16x2(v0 - f16lo(hi2), v1 - f16hi(hi2));
                uint2 o; o.x = hi2; o.y = lo2;
                *(uint2*)(dstb + ((size_t)b * N_ + n_row0 + h * 8) * 64 + off) = o;
            }
        }
    } else {
        // C frag: rows d = (rg-1)*128 + w*16 + gr (+8); cols n = nt*8+2tg,+1
        const int d0 = (rg - 1) * 128 + w * 16 + gr;
        uint32_t* Hb = (uint32_t*)g_H + (size_t)b * C_ * 2048;
#pragma unroll
        for (int nt = 0; nt < 16; nt++) {
            const int P = (nb0 >> 1) + nt * 4 + tg;          // m-pair index
            const int pt = P & 15, qb = pt & 7;
            const int pos = (P & ~15) + (pt >> 3) * 8 + (qb & 3) * 2 + (qb >> 2);
            Hb[(size_t)d0 * 2048 + pos]       = f16x2(acc[nt][0], acc[nt][1]);
            Hb[(size_t)(d0 + 8) * 2048 + pos] = f16x2(acc[nt][2], acc[nt][3]);
        }
    }
}

// ---------------------------------------------------------------------------
// fp16 hi/lo flash attention — UNCHANGED from the best passing round-8 kernel
// (448.8 us, rel_err 9.25e-5). 256 thr, 128 q-rows, MT=32, cp.async dbl-buf,
// S 3-pass fp16 k16 (LDS.128 frags), PV 1-pass fp16 (LDS.64 frags).
// ---------------------------------------------------------------------------
#define GROW 80                          // u32 per G/F smem row (64 + 16 pad)
#define HROW 24                          // u32 per H smem row (16 + 8 pad)
#define SG  0
#define SF  (128 * GROW)                 // 10240
#define FPL (MT * GROW)                  // 2560
#define SH  (SF + 2 * FPL)               // 15360
#define HPL (C_ * HROW)                  // 6144
#define SMEMU (SH + 2 * HPL)             // 27648 u32
#define SMEMB (SMEMU * 4)                // 110592 B

__global__ __launch_bounds__(256, 1) void attn_kernel(
    const float* __restrict__ input,
    const float* __restrict__ gamma_p,
    float* __restrict__ out)
{
    extern __shared__ uint32_t sm[];
    uint32_t smu;
    asm("{ .reg .u64 t; cvta.to.shared.u64 t, %1; cvt.u32.u64 %0, t; }"
        : "=r"(smu) : "l"(sm));

    const int tid  = threadIdx.x;
    const int lane = tid & 31;
    const int w    = tid >> 5;
    const int gr   = lane >> 2;
    const int tg   = lane & 3;
    const int n0   = blockIdx.x * 128;
    const int b    = blockIdx.y;

    const uint32_t* FG = g_F + (size_t)b * N_ * 64;
    const uint32_t* HG = (const uint32_t*)(g_H + (size_t)b * C_ * N_);

    // stage G tile (128 rows x 64 u32) once via cp.async
    {
        const uint32_t* GG = g_G + ((size_t)b * N_ + n0) * 64;
        for (int i = tid; i < 128 * 16; i += 256) {
            int r = i >> 4, ch = i & 15;
            cp16(smu + (SG + r * GROW + ch * 4) * 4, GG + r * 64 + ch * 4);
        }
    }
    // prefetch m-tile 0 into buf 0
    {
        for (int i = tid; i < 512; i += 256) {
            int r = i >> 4, ch = i & 15;
            cp16(smu + (SF + r * GROW + ch * 4) * 4, FG + (size_t)r * 64 + ch * 4);
        }
        for (int i = tid; i < 1024; i += 256) {
            int r = i >> 2, ch = i & 3;   // r = d 0..255
            cp16(smu + (SH + r * HROW + ch * 4) * 4, HG + (size_t)r * 2048 + ch * 4);
        }
        cp_commit();
    }

    float oacc[32][4];
#pragma unroll
    for (int i = 0; i < 32; i++) {
        oacc[i][0] = 0.f; oacc[i][1] = 0.f; oacc[i][2] = 0.f; oacc[i][3] = 0.f;
    }
    const float NEG_INF = __int_as_float(0xff800000);
    float mrow0 = NEG_INF, mrow1 = NEG_INF, lsum0 = 0.f, lsum1 = 0.f;

    const uint32_t* g0 = sm + SG + (w * 16 + gr) * GROW;

#pragma unroll 1
    for (int t = 0; t < N_ / MT; t++) {
        cp_wait0();
        __syncthreads();

        const int cur = t & 1;
        if (t + 1 < N_ / MT) {
            const int m0n = (t + 1) * MT;
            const int nb = cur ^ 1;
            for (int i = tid; i < 512; i += 256) {
                int r = i >> 4, ch = i & 15;
                cp16(smu + (SF + nb * FPL + r * GROW + ch * 4) * 4,
                     FG + (size_t)(m0n + r) * 64 + ch * 4);
            }
            for (int i = tid; i < 1024; i += 256) {
                int r = i >> 2, ch = i & 3;
                cp16(smu + (SH + nb * HPL + r * HROW + ch * 4) * 4,
                     HG + (size_t)r * 2048 + m0n / 2 + ch * 4);
            }
            cp_commit();
        }

        const uint32_t* sFc = sm + SF + cur * FPL;
        const uint32_t* sHc = sm + SH + cur * HPL;

        // ---- S tile: 3-pass fp16 k16; frags via LDS.128 (permuted) ----
        float sc[4][4];
#pragma unroll
        for (int ms = 0; ms < 4; ms++) {
            sc[ms][0] = 0.f; sc[ms][1] = 0.f; sc[ms][2] = 0.f; sc[ms][3] = 0.f;
        }
#pragma unroll
        for (int kc = 0; kc < 4; kc++) {
            const uint32_t* ga = g0 + kc * 16 + 4 * tg;
            uint4 Aa = *(const uint4*)ga;               // A0h,A0l,A2h,A2l
            uint4 Ab = *(const uint4*)(ga + 8 * GROW);  // A1h,A1l,A3h,A3l
#pragma unroll
            for (int ms = 0; ms < 4; ms++) {
                const uint32_t* f = sFc + (ms * 8 + gr) * GROW + kc * 16 + 4 * tg;
                uint4 Bv = *(const uint4*)f;            // B0h,B0l,B1h,B1l
                mma_f16(sc[ms], Aa.x, Ab.x, Aa.z, Ab.z, Bv.x, Bv.z);
                mma_f16(sc[ms], Aa.x, Ab.x, Aa.z, Ab.z, Bv.y, Bv.w);
                mma_f16(sc[ms], Aa.y, Ab.y, Aa.w, Ab.w, Bv.x, Bv.z);
            }
        }

        // ---- online softmax (log2 domain), lazy O-rescale ----
        float t0 = NEG_INF, t1 = NEG_INF;
#pragma unroll
        for (int ms = 0; ms < 4; ms++) {
            t0 = fmaxf(t0, fmaxf(sc[ms][0], sc[ms][1]));
            t1 = fmaxf(t1, fmaxf(sc[ms][2], sc[ms][3]));
        }
        t0 = fmaxf(t0, __shfl_xor_sync(0xffffffffu, t0, 1));
        t0 = fmaxf(t0, __shfl_xor_sync(0xffffffffu, t0, 2));
        t1 = fmaxf(t1, __shfl_xor_sync(0xffffffffu, t1, 1));
        t1 = fmaxf(t1, __shfl_xor_sync(0xffffffffu, t1, 2));

        const float mn0 = fmaxf(mrow0, t0);
        const float mn1 = fmaxf(mrow1, t1);
        const bool up = (mn0 != mrow0) || (mn1 != mrow1);
        if (__any_sync(0xffffffffu, up)) {
            const float cr0 = ex2(mrow0 - mn0);
            const float cr1 = ex2(mrow1 - mn1);
            lsum0 *= cr0; lsum1 *= cr1;
#pragma unroll
            for (int dt = 0; dt < 32; dt++) {
                oacc[dt][0] *= cr0; oacc[dt][1] *= cr0;
                oacc[dt][2] *= cr1; oacc[dt][3] *= cr1;
            }
            mrow0 = mn0; mrow1 = mn1;
        }
#pragma unroll
        for (int ms = 0; ms < 4; ms++) {
            sc[ms][0] = ex2(sc[ms][0] - mrow0);
            sc[ms][1] = ex2(sc[ms][1] - mrow0);
            sc[ms][2] = ex2(sc[ms][2] - mrow1);
            sc[ms][3] = ex2(sc[ms][3] - mrow1);
            lsum0 += sc[ms][0] + sc[ms][1];
            lsum1 += sc[ms][2] + sc[ms][3];
        }

        // ---- PV: O += P * H, 1-pass fp16; B-frags via LDS.64 (permuted) ----
#pragma unroll
        for (int j = 0; j < 2; j++) {
            const float* cA = sc[2 * j];
            const float* cB = sc[2 * j + 1];
            uint32_t p0 = f16x2(cA[0], cA[1]);
            uint32_t p1 = f16x2(cA[2], cA[3]);
            uint32_t p2 = f16x2(cB[0], cB[1]);
            uint32_t p3 = f16x2(cB[2], cB[3]);
            const uint32_t* hb = sHc + gr * HROW + j * 8 + 2 * tg;
#pragma unroll
            for (int dt = 0; dt < 32; dt++) {
                uint2 bv = *(const uint2*)(hb + dt * 8 * HROW);
                mma_f16(oacc[dt], p0, p1, p2, p3, bv.x, bv.y);
            }
        }
    }

    // ---- epilogue: l reduce, out = gamma*(O/l) + input, flat [B,N,C] ----
    lsum0 += __shfl_xor_sync(0xffffffffu, lsum0, 1);
    lsum0 += __shfl_xor_sync(0xffffffffu, lsum0, 2);
    lsum1 += __shfl_xor_sync(0xffffffffu, lsum1, 1);
    lsum1 += __shfl_xor_sync(0xffffffffu, lsum1, 2);
    const float inv0 = 1.0f / lsum0;
    const float inv1 = 1.0f / lsum1;
    const float gm = __ldg(gamma_p);

    const int r0 = n0 + w * 16 + gr;
    const int r1 = r0 + 8;
    const size_t base0 = ((size_t)b * N_ + r0) * C_ + tg * 2;
    const size_t base1 = ((size_t)b * N_ + r1) * C_ + tg * 2;
#pragma unroll
    for (int dt = 0; dt < 32; dt++) {
        float2 iv0 = *(const float2*)(input + base0 + dt * 8);
        float2 iv1 = *(const float2*)(input + base1 + dt * 8);
        float2 ov0, ov1;
        ov0.x = fmaf(gm, oacc[dt][0] * inv0, iv0.x);
        ov0.y = fmaf(gm, oacc[dt][1] * inv0, iv0.y);
        ov1.x = fmaf(gm, oacc[dt][2] * inv1, iv1.x);
        ov1.y = fmaf(gm, oacc[dt][3] * inv1, iv1.y);
        *(float2*)(out + base0 + dt * 8) = ov0;
        *(float2*)(out + base1 + dt * 8) = ov1;
    }
}

// ---------------------------------------------------------------------------
extern "C" void kernel_launch(void* const* d_in, const int* in_sizes, int n_in,
                              void* d_out, int out_size) {
    (void)in_sizes; (void)n_in; (void)out_size;
    const float* input = (const float*)d_in[0];
    const float* feat  = (const float*)d_in[1];   // nms_feat
    const float* WF    = (const float*)d_in[2];
    const float* WG    = (const float*)d_in[3];
    const float* WH    = (const float*)d_in[4];
    const float* gamma = (const float*)d_in[5];
    float* out = (float*)d_out;

    cudaFuncSetAttribute(proj_kernel,
                         cudaFuncAttributeMaxDynamicSharedMemorySize, PSMEMB);
    cudaFuncSetAttribute(attn_kernel,
                         cudaFuncAttributeMaxDynamicSharedMemorySize, SMEMB);

    proj_kernel<<<dim3(N_ / 128, 3, B_), 256, PSMEMB>>>(feat, WF, WG, WH);
    attn_kernel<<<dim3(N_ / 128, B_), 256, SMEMB>>>(input, gamma, out);
}

// round 14
// speedup vs baseline: 1.1103x; 1.0842x over previous
#include <cuda_runtime.h>
#include <cuda_fp16.h>
#include <cstdint>

#define B_ 8
#define C_ 256
#define N_ 4096
#define K_ 64
#define MT 32
#define LOG2E 1.4426950408889634f

// Scratch (fp16 hi/lo packed), PERMUTED for wide LDS fragment loads.
// F/G row (per n): 32 k-pairs in 4 blocks of 8; within a block, pair qb is
// stored at position perm(qb) = (qb&3)*2 + (qb>>2); each position = (hi,lo).
// H: fp16 single, transposed [b][d][m-pairs], same per-8-block permutation.
__device__ uint32_t g_F[(size_t)B_ * N_ * 64];
__device__ uint32_t g_G[(size_t)B_ * N_ * 64];     // pre-scaled by log2(e)
__device__ uint16_t g_H[(size_t)B_ * C_ * N_];

// ---------------- helpers ----------------
__device__ __forceinline__ uint32_t f16x2(float lo, float hi) {
    uint32_t r;
    asm("cvt.rn.f16x2.f32 %0, %1, %2;" : "=r"(r) : "f"(hi), "f"(lo));
    return r;
}
__device__ __forceinline__ float f16lo(uint32_t p) {
    return __half2float(__ushort_as_half((unsigned short)(p & 0xffffu)));
}
__device__ __forceinline__ float f16hi(uint32_t p) {
    return __half2float(__ushort_as_half((unsigned short)(p >> 16)));
}
__device__ __forceinline__ float ex2(float x) {
    float r; asm("ex2.approx.f32 %0, %1;" : "=f"(r) : "f"(x)); return r;
}
__device__ __forceinline__ void mma_f16(float* c,
    uint32_t a0, uint32_t a1, uint32_t a2, uint32_t a3,
    uint32_t b0, uint32_t b1) {
    asm volatile("mma.sync.aligned.m16n8k16.row.col.f32.f16.f16.f32 "
        "{%0,%1,%2,%3},{%4,%5,%6,%7},{%8,%9},{%0,%1,%2,%3};"
        : "+f"(c[0]), "+f"(c[1]), "+f"(c[2]), "+f"(c[3])
        : "r"(a0), "r"(a1), "r"(a2), "r"(a3), "r"(b0), "r"(b1));
}
__device__ __forceinline__ void cp16(uint32_t dst, const void* src) {
    asm volatile("cp.async.cg.shared.global [%0], [%1], 16;" :: "r"(dst), "l"(src));
}
__device__ __forceinline__ void cp_commit() { asm volatile("cp.async.commit_group;"); }
__device__ __forceinline__ void cp_wait0()  { asm volatile("cp.async.wait_group 0;"); }

// pair permutation within an 8-pair block: u32 offset of pair p inside a
// 64-u32 row (4 blocks of 16 u32; each pair = (hi,lo) adjacent)
__device__ __forceinline__ int pair_off(int p) {
    int qb = p & 7;
    return (p >> 3) * 16 + ((qb & 3) * 2 + (qb >> 2)) * 2;
}

// ---------------------------------------------------------------------------
// Tensor-core projection, fully-coalesced I/O. Block = 256 thr, grid (32,3,B).
//  rg=0 : FG mode — A = feat rows (128 n), B = [WF;WG] rows (128 r)
//  rg=1,2: H mode — A = WH rows (128 d),  B = feat rows (128 n)
// MMA identical to round 12. NEW: W staged via linear float4 (no replays);
// epilogue stages C-frags in smem then copies out as contiguous uint4 rows.
// ---------------------------------------------------------------------------
#define PGROW 80
#define PSMEMB (2 * 128 * PGROW * 4)     // 81920 B (>= epilogue: 128*132*4)

__global__ __launch_bounds__(256, 2) void proj_kernel(
    const float* __restrict__ feat,
    const float* __restrict__ WF,
    const float* __restrict__ WG,
    const float* __restrict__ WH)
{
    extern __shared__ uint32_t psm[];
    uint32_t* sA = psm;                  // A rows (n for FG, d for H)
    uint32_t* sB = psm + 128 * PGROW;    // B rows (r for FG, n for H)

    const int tid  = threadIdx.x;
    const int lane = tid & 31;
    const int w    = tid >> 5;
    const int gr   = lane >> 2;
    const int tg   = lane & 3;
    const int nb0  = blockIdx.x * 128;
    const int rg   = blockIdx.y;
    const int b    = blockIdx.z;
    const bool modeH = (rg > 0);
    const float* fb = feat + (size_t)b * C_ * N_;

    float acc[16][4];
#pragma unroll
    for (int i = 0; i < 16; i++) {
        acc[i][0] = 0.f; acc[i][1] = 0.f; acc[i][2] = 0.f; acc[i][3] = 0.f;
    }

#pragma unroll 1
    for (int kt = 0; kt < 4; kt++) {
        const int c0 = kt * 64;
        __syncthreads();

        // ---- stage feat tile (128 n x 64 c): coalesced over n ----
        {
            uint32_t* dst = modeH ? sB : sA;
            const int n_i  = tid & 127;
            const int half = tid >> 7;                 // c-half 0/1
            uint32_t* row = dst + n_i * PGROW;
            const float* fp = fb + (size_t)(c0 + half * 32) * N_ + nb0 + n_i;
#pragma unroll
            for (int p = 0; p < 16; p++) {
                float x0 = fp[(size_t)(2 * p) * N_];
                float x1 = fp[(size_t)(2 * p + 1) * N_];
                uint32_t hi2 = f16x2(x0, x1);
                uint32_t lo2 = f16x2(x0 - f16lo(hi2), x1 - f16hi(hi2));
                uint2 o; o.x = hi2; o.y = lo2;
                *(uint2*)(row + pair_off(half * 16 + p)) = o;
            }
        }
        // ---- stage W tile (128 r x 64 c): linear float4, no replays ----
        {
            uint32_t* dst = modeH ? sA : sB;
#pragma unroll
            for (int i = 0; i < 8; i++) {
                const int idx = tid + i * 256;         // 0..2047
                const int r = idx >> 4, f4 = idx & 15;
                const float* Wr;
                if (modeH) Wr = WH + (size_t)((rg - 1) * 128 + r) * C_;
                else       Wr = (r < 64) ? WF + (size_t)r * C_
                                         : WG + (size_t)(r - 64) * C_;
                float4 x = __ldg((const float4*)(Wr + c0 + f4 * 4));
                uint32_t h0 = f16x2(x.x, x.y);
                uint32_t l0 = f16x2(x.x - f16lo(h0), x.y - f16hi(h0));
                uint32_t h1 = f16x2(x.z, x.w);
                uint32_t l1 = f16x2(x.z - f16lo(h1), x.w - f16hi(h1));
                uint32_t* row = dst + r * PGROW;
                uint2 o0; o0.x = h0; o0.y = l0;
                uint2 o1; o1.x = h1; o1.y = l1;
                *(uint2*)(row + pair_off(2 * f4))     = o0;
                *(uint2*)(row + pair_off(2 * f4 + 1)) = o1;
            }
        }
        __syncthreads();

        // ---- MMA: 3-pass hi/lo (identical to round 12) ----
        const uint32_t* ga = sA + (w * 16 + gr) * PGROW;
#pragma unroll
        for (int kc = 0; kc < 4; kc++) {
            const int o0 = kc * 16 + 4 * tg;
            uint4 Aa = *(const uint4*)(ga + o0);
            uint4 Ab = *(const uint4*)(ga + 8 * PGROW + o0);
#pragma unroll
            for (int t8 = 0; t8 < 16; t8++) {
                const uint32_t* f = sB + (t8 * 8 + gr) * PGROW + o0;
                uint4 Bv = *(const uint4*)f;
                mma_f16(acc[t8], Aa.x, Ab.x, Aa.z, Ab.z, Bv.x, Bv.z);
                mma_f16(acc[t8], Aa.x, Ab.x, Aa.z, Ab.z, Bv.y, Bv.w);
                mma_f16(acc[t8], Aa.y, Ab.y, Aa.w, Ab.w, Bv.x, Bv.z);
            }
        }
    }
    __syncthreads();        // smem free for epilogue staging

    if (!modeH) {
        // ---- FG epilogue: frags -> smem rows (132 u32: F[0:64) G[64:128)) ----
        const int nloc0 = w * 16 + gr;
#pragma unroll
        for (int t8 = 0; t8 < 16; t8++) {
            const bool isG = (t8 >= 8);
            const float scale = isG ? LOG2E : 1.0f;
            const int pk = t8 * 4 + tg;
            const int off = (isG ? 64 + pair_off(pk - 32) : pair_off(pk));
#pragma unroll
            for (int h = 0; h < 2; h++) {
                float v0 = acc[t8][2 * h] * scale;
                float v1 = acc[t8][2 * h + 1] * scale;
                uint32_t hi2 = f16x2(v0, v1);
                uint32_t lo2 = f16x2(v0 - f16lo(hi2), v1 - f16hi(hi2));
                uint2 o; o.x = hi2; o.y = lo2;
                *(uint2*)(psm + (nloc0 + h * 8) * 132 + off) = o;
            }
        }
        __syncthreads();
        // ---- coalesced copy-out: 256B contiguous per n-row ----
#pragma unroll
        for (int i = 0; i < 8; i++) {
            const int idx = tid + i * 256;             // 0..2047
            const int row = idx >> 4, q4 = idx & 15;
            const size_t drow = ((size_t)b * N_ + nb0 + row) * 64 + q4 * 4;
            uint4 vf = *(const uint4*)(psm + row * 132 + q4 * 4);
            uint4 vg = *(const uint4*)(psm + row * 132 + 64 + q4 * 4);
            *(uint4*)(g_F + drow) = vf;
            *(uint4*)(g_G + drow) = vg;
        }
    } else {
        // ---- H epilogue: frags -> smem rows (68 u32), then linear copy ----
        const int dloc0 = w * 16 + gr;
#pragma unroll
        for (int nt = 0; nt < 16; nt++) {
            const int Pl = nt * 4 + tg;                // local m-pair 0..63
            const int qb = Pl & 7;
            const int posl = (Pl & ~15) + ((Pl >> 3) & 1) * 8
                           + (qb & 3) * 2 + (qb >> 2);
            psm[dloc0 * 68 + posl]       = f16x2(acc[nt][0], acc[nt][1]);
            psm[(dloc0 + 8) * 68 + posl] = f16x2(acc[nt][2], acc[nt][3]);
        }
        __syncthreads();
        uint32_t* Hb = (uint32_t*)g_H + (size_t)b * C_ * 2048;
#pragma unroll
        for (int i = 0; i < 8; i++) {
            const int idx = tid + i * 256;             // 0..2047
            const int row = idx >> 4, q4 = idx & 15;
            uint4 v = *(const uint4*)(psm + row * 68 + q4 * 4);
            *(uint4*)(Hb + (size_t)((rg - 1) * 128 + row) * 2048
                      + nb0 / 2 + q4 * 4) = v;
        }
    }
}

// ---------------------------------------------------------------------------
// fp16 hi/lo flash attention — UNCHANGED (best passing: 448.8 us, 9.25e-5).
// 256 thr, 128 q-rows, MT=32, cp.async dbl-buf, S 3-pass fp16 k16 (LDS.128),
// PV 1-pass fp16 (LDS.64).
// ---------------------------------------------------------------------------
#define GROW 80
#define HROW 24
#define SG  0
#define SF  (128 * GROW)
#define FPL (MT * GROW)
#define SH  (SF + 2 * FPL)
#define HPL (C_ * HROW)
#define SMEMU (SH + 2 * HPL)
#define SMEMB (SMEMU * 4)

__global__ __launch_bounds__(256, 1) void attn_kernel(
    const float* __restrict__ input,
    const float* __restrict__ gamma_p,
    float* __restrict__ out)
{
    extern __shared__ uint32_t sm[];
    uint32_t smu;
    asm("{ .reg .u64 t; cvta.to.shared.u64 t, %1; cvt.u32.u64 %0, t; }"
        : "=r"(smu) : "l"(sm));

    const int tid  = threadIdx.x;
    const int lane = tid & 31;
    const int w    = tid >> 5;
    const int gr   = lane >> 2;
    const int tg   = lane & 3;
    const int n0   = blockIdx.x * 128;
    const int b    = blockIdx.y;

    const uint32_t* FG = g_F + (size_t)b * N_ * 64;
    const uint32_t* HG = (const uint32_t*)(g_H + (size_t)b * C_ * N_);

    {
        const uint32_t* GG = g_G + ((size_t)b * N_ + n0) * 64;
        for (int i = tid; i < 128 * 16; i += 256) {
            int r = i >> 4, ch = i & 15;
            cp16(smu + (SG + r * GROW + ch * 4) * 4, GG + r * 64 + ch * 4);
        }
    }
    {
        for (int i = tid; i < 512; i += 256) {
            int r = i >> 4, ch = i & 15;
            cp16(smu + (SF + r * GROW + ch * 4) * 4, FG + (size_t)r * 64 + ch * 4);
        }
        for (int i = tid; i < 1024; i += 256) {
            int r = i >> 2, ch = i & 3;
            cp16(smu + (SH + r * HROW + ch * 4) * 4, HG + (size_t)r * 2048 + ch * 4);
        }
        cp_commit();
    }

    float oacc[32][4];
#pragma unroll
    for (int i = 0; i < 32; i++) {
        oacc[i][0] = 0.f; oacc[i][1] = 0.f; oacc[i][2] = 0.f; oacc[i][3] = 0.f;
    }
    const float NEG_INF = __int_as_float(0xff800000);
    float mrow0 = NEG_INF, mrow1 = NEG_INF, lsum0 = 0.f, lsum1 = 0.f;

    const uint32_t* g0 = sm + SG + (w * 16 + gr) * GROW;

#pragma unroll 1
    for (int t = 0; t < N_ / MT; t++) {
        cp_wait0();
        __syncthreads();

        const int cur = t & 1;
        if (t + 1 < N_ / MT) {
            const int m0n = (t + 1) * MT;
            const int nb = cur ^ 1;
            for (int i = tid; i < 512; i += 256) {
                int r = i >> 4, ch = i & 15;
                cp16(smu + (SF + nb * FPL + r * GROW + ch * 4) * 4,
                     FG + (size_t)(m0n + r) * 64 + ch * 4);
            }
            for (int i = tid; i < 1024; i += 256) {
                int r = i >> 2, ch = i & 3;
                cp16(smu + (SH + nb * HPL + r * HROW + ch * 4) * 4,
                     HG + (size_t)r * 2048 + m0n / 2 + ch * 4);
            }
            cp_commit();
        }

        const uint32_t* sFc = sm + SF + cur * FPL;
        const uint32_t* sHc = sm + SH + cur * HPL;

        float sc[4][4];
#pragma unroll
        for (int ms = 0; ms < 4; ms++) {
            sc[ms][0] = 0.f; sc[ms][1] = 0.f; sc[ms][2] = 0.f; sc[ms][3] = 0.f;
        }
#pragma unroll
        for (int kc = 0; kc < 4; kc++) {
            const uint32_t* ga = g0 + kc * 16 + 4 * tg;
            uint4 Aa = *(const uint4*)ga;
            uint4 Ab = *(const uint4*)(ga + 8 * GROW);
#pragma unroll
            for (int ms = 0; ms < 4; ms++) {
                const uint32_t* f = sFc + (ms * 8 + gr) * GROW + kc * 16 + 4 * tg;
                uint4 Bv = *(const uint4*)f;
                mma_f16(sc[ms], Aa.x, Ab.x, Aa.z, Ab.z, Bv.x, Bv.z);
                mma_f16(sc[ms], Aa.x, Ab.x, Aa.z, Ab.z, Bv.y, Bv.w);
                mma_f16(sc[ms], Aa.y, Ab.y, Aa.w, Ab.w, Bv.x, Bv.z);
            }
        }

        float t0 = NEG_INF, t1 = NEG_INF;
#pragma unroll
        for (int ms = 0; ms < 4; ms++) {
            t0 = fmaxf(t0, fmaxf(sc[ms][0], sc[ms][1]));
            t1 = fmaxf(t1, fmaxf(sc[ms][2], sc[ms][3]));
        }
        t0 = fmaxf(t0, __shfl_xor_sync(0xffffffffu, t0, 1));
        t0 = fmaxf(t0, __shfl_xor_sync(0xffffffffu, t0, 2));
        t1 = fmaxf(t1, __shfl_xor_sync(0xffffffffu, t1, 1));
        t1 = fmaxf(t1, __shfl_xor_sync(0xffffffffu, t1, 2));

        const float mn0 = fmaxf(mrow0, t0);
        const float mn1 = fmaxf(mrow1, t1);
        const bool up = (mn0 != mrow0) || (mn1 != mrow1);
        if (__any_sync(0xffffffffu, up)) {
            const float cr0 = ex2(mrow0 - mn0);
            const float cr1 = ex2(mrow1 - mn1);
            lsum0 *= cr0; lsum1 *= cr1;
#pragma unroll
            for (int dt = 0; dt < 32; dt++) {
                oacc[dt][0] *= cr0; oacc[dt][1] *= cr0;
                oacc[dt][2] *= cr1; oacc[dt][3] *= cr1;
            }
            mrow0 = mn0; mrow1 = mn1;
        }
#pragma unroll
        for (int ms = 0; ms < 4; ms++) {
            sc[ms][0] = ex2(sc[ms][0] - mrow0);
            sc[ms][1] = ex2(sc[ms][1] - mrow0);
            sc[ms][2] = ex2(sc[ms][2] - mrow1);
            sc[ms][3] = ex2(sc[ms][3] - mrow1);
            lsum0 += sc[ms][0] + sc[ms][1];
            lsum1 += sc[ms][2] + sc[ms][3];
        }

#pragma unroll
        for (int j = 0; j < 2; j++) {
            const float* cA = sc[2 * j];
            const float* cB = sc[2 * j + 1];
            uint32_t p0 = f16x2(cA[0], cA[1]);
            uint32_t p1 = f16x2(cA[2], cA[3]);
            uint32_t p2 = f16x2(cB[0], cB[1]);
            uint32_t p3 = f16x2(cB[2], cB[3]);
            const uint32_t* hb = sHc + gr * HROW + j * 8 + 2 * tg;
#pragma unroll
            for (int dt = 0; dt < 32; dt++) {
                uint2 bv = *(const uint2*)(hb + dt * 8 * HROW);
                mma_f16(oacc[dt], p0, p1, p2, p3, bv.x, bv.y);
            }
        }
    }

    lsum0 += __shfl_xor_sync(0xffffffffu, lsum0, 1);
    lsum0 += __shfl_xor_sync(0xffffffffu, lsum0, 2);
    lsum1 += __shfl_xor_sync(0xffffffffu, lsum1, 1);
    lsum1 += __shfl_xor_sync(0xffffffffu, lsum1, 2);
    const float inv0 = 1.0f / lsum0;
    const float inv1 = 1.0f / lsum1;
    const float gm = __ldg(gamma_p);

    const int r0 = n0 + w * 16 + gr;
    const int r1 = r0 + 8;
    const size_t base0 = ((size_t)b * N_ + r0) * C_ + tg * 2;
    const size_t base1 = ((size_t)b * N_ + r1) * C_ + tg * 2;
#pragma unroll
    for (int dt = 0; dt < 32; dt++) {
        float2 iv0 = *(const float2*)(input + base0 + dt * 8);
        float2 iv1 = *(const float2*)(input + base1 + dt * 8);
        float2 ov0, ov1;
        ov0.x = fmaf(gm, oacc[dt][0] * inv0, iv0.x);
        ov0.y = fmaf(gm, oacc[dt][1] * inv0, iv0.y);
        ov1.x = fmaf(gm, oacc[dt][2] * inv1, iv1.x);
        ov1.y = fmaf(gm, oacc[dt][3] * inv1, iv1.y);
        *(float2*)(out + base0 + dt * 8) = ov0;
        *(float2*)(out + base1 + dt * 8) = ov1;
    }
}

// ---------------------------------------------------------------------------
extern "C" void kernel_launch(void* const* d_in, const int* in_sizes, int n_in,
                              void* d_out, int out_size) {
    (void)in_sizes; (void)n_in; (void)out_size;
    const float* input = (const float*)d_in[0];
    const float* feat  = (const float*)d_in[1];   // nms_feat
    const float* WF    = (const float*)d_in[2];
    const float* WG    = (const float*)d_in[3];
    const float* WH    = (const float*)d_in[4];
    const float* gamma = (const float*)d_in[5];
    float* out = (float*)d_out;

    cudaFuncSetAttribute(proj_kernel,
                         cudaFuncAttributeMaxDynamicSharedMemorySize, PSMEMB);
    cudaFuncSetAttribute(attn_kernel,
                         cudaFuncAttributeMaxDynamicSharedMemorySize, SMEMB);

    proj_kernel<<<dim3(N_ / 128, 3, B_), 256, PSMEMB>>>(feat, WF, WG, WH);
    attn_kernel<<<dim3(N_ / 128, B_), 256, SMEMB>>>(input, gamma, out);
}

// round 15
// speedup vs baseline: 1.2525x; 1.1281x over previous
#include <cuda_runtime.h>
#include <cuda_fp16.h>
#include <cstdint>

#define B_ 8
#define C_ 256
#define N_ 4096
#define K_ 64
#define MT 32
#define LOG2E 1.4426950408889634f

// g_F: fp16 HI ONLY, tg-major rows of 32 u32: k-pair p (kc=p>>3, qb=p&7,
//      tg=qb&3, slot=qb>>2) stored at position tg*8 + kc*2 + slot.
// g_G: fp16 hi/lo interleaved, permuted rows of 64 u32 (unchanged).
// g_H: fp16 single, transposed [b][d][m-pairs], permuted (unchanged).
__device__ uint32_t g_F[(size_t)B_ * N_ * 32];
__device__ uint32_t g_G[(size_t)B_ * N_ * 64];     // pre-scaled by log2(e)
__device__ uint16_t g_H[(size_t)B_ * C_ * N_];

// ---------------- helpers ----------------
__device__ __forceinline__ uint32_t f16x2(float lo, float hi) {
    uint32_t r;
    asm("cvt.rn.f16x2.f32 %0, %1, %2;" : "=r"(r) : "f"(hi), "f"(lo));
    return r;
}
__device__ __forceinline__ float f16lo(uint32_t p) {
    return __half2float(__ushort_as_half((unsigned short)(p & 0xffffu)));
}
__device__ __forceinline__ float f16hi(uint32_t p) {
    return __half2float(__ushort_as_half((unsigned short)(p >> 16)));
}
__device__ __forceinline__ float ex2(float x) {
    float r; asm("ex2.approx.f32 %0, %1;" : "=f"(r) : "f"(x)); return r;
}
__device__ __forceinline__ void mma_f16(float* c,
    uint32_t a0, uint32_t a1, uint32_t a2, uint32_t a3,
    uint32_t b0, uint32_t b1) {
    asm volatile("mma.sync.aligned.m16n8k16.row.col.f32.f16.f16.f32 "
        "{%0,%1,%2,%3},{%4,%5,%6,%7},{%8,%9},{%0,%1,%2,%3};"
        : "+f"(c[0]), "+f"(c[1]), "+f"(c[2]), "+f"(c[3])
        : "r"(a0), "r"(a1), "r"(a2), "r"(a3), "r"(b0), "r"(b1));
}
__device__ __forceinline__ void cp16(uint32_t dst, const void* src) {
    asm volatile("cp.async.cg.shared.global [%0], [%1], 16;" :: "r"(dst), "l"(src));
}
__device__ __forceinline__ void cp_commit() { asm volatile("cp.async.commit_group;"); }
__device__ __forceinline__ void cp_wait0()  { asm volatile("cp.async.wait_group 0;"); }

// G-layout pair permutation (unchanged): u32 offset of pair p in a 64-u32 row
__device__ __forceinline__ int pair_off(int p) {
    int qb = p & 7;
    return (p >> 3) * 16 + ((qb & 3) * 2 + (qb >> 2)) * 2;
}
// F-layout (hi-only, tg-major): u32 offset of pair p in a 32-u32 row
__device__ __forceinline__ int fpos(int p) {
    int qb = p & 7;
    return (qb & 3) * 8 + (p >> 3) * 2 + (qb >> 2);
}

// ---------------------------------------------------------------------------
// Tensor-core projection, coalesced I/O (round-13 structure).
//  rg=0 : FG mode — A = feat rows (128 n), B = [WF;WG] rows (128 r)
//  rg=1,2: H mode — A = WH rows (128 d),  B = feat rows (128 n)
// F epilogue now writes hi-only tg-major rows (32 u32).
// ---------------------------------------------------------------------------
#define PGROW 80
#define PSMEMB (2 * 128 * PGROW * 4)     // 81920 B

__global__ __launch_bounds__(256, 2) void proj_kernel(
    const float* __restrict__ feat,
    const float* __restrict__ WF,
    const float* __restrict__ WG,
    const float* __restrict__ WH)
{
    extern __shared__ uint32_t psm[];
    uint32_t* sA = psm;
    uint32_t* sB = psm + 128 * PGROW;

    const int tid  = threadIdx.x;
    const int lane = tid & 31;
    const int w    = tid >> 5;
    const int gr   = lane >> 2;
    const int tg   = lane & 3;
    const int nb0  = blockIdx.x * 128;
    const int rg   = blockIdx.y;
    const int b    = blockIdx.z;
    const bool modeH = (rg > 0);
    const float* fb = feat + (size_t)b * C_ * N_;

    float acc[16][4];
#pragma unroll
    for (int i = 0; i < 16; i++) {
        acc[i][0] = 0.f; acc[i][1] = 0.f; acc[i][2] = 0.f; acc[i][3] = 0.f;
    }

#pragma unroll 1
    for (int kt = 0; kt < 4; kt++) {
        const int c0 = kt * 64;
        __syncthreads();

        {   // stage feat tile (coalesced over n)
            uint32_t* dst = modeH ? sB : sA;
            const int n_i  = tid & 127;
            const int half = tid >> 7;
            uint32_t* row = dst + n_i * PGROW;
            const float* fp = fb + (size_t)(c0 + half * 32) * N_ + nb0 + n_i;
#pragma unroll
            for (int p = 0; p < 16; p++) {
                float x0 = fp[(size_t)(2 * p) * N_];
                float x1 = fp[(size_t)(2 * p + 1) * N_];
                uint32_t hi2 = f16x2(x0, x1);
                uint32_t lo2 = f16x2(x0 - f16lo(hi2), x1 - f16hi(hi2));
                uint2 o; o.x = hi2; o.y = lo2;
                *(uint2*)(row + pair_off(half * 16 + p)) = o;
            }
        }
        {   // stage W tile (linear float4)
            uint32_t* dst = modeH ? sA : sB;
#pragma unroll
            for (int i = 0; i < 8; i++) {
                const int idx = tid + i * 256;
                const int r = idx >> 4, f4 = idx & 15;
                const float* Wr;
                if (modeH) Wr = WH + (size_t)((rg - 1) * 128 + r) * C_;
                else       Wr = (r < 64) ? WF + (size_t)r * C_
                                         : WG + (size_t)(r - 64) * C_;
                float4 x = __ldg((const float4*)(Wr + c0 + f4 * 4));
                uint32_t h0 = f16x2(x.x, x.y);
                uint32_t l0 = f16x2(x.x - f16lo(h0), x.y - f16hi(h0));
                uint32_t h1 = f16x2(x.z, x.w);
                uint32_t l1 = f16x2(x.z - f16lo(h1), x.w - f16hi(h1));
                uint32_t* row = dst + r * PGROW;
                uint2 o0; o0.x = h0; o0.y = l0;
                uint2 o1; o1.x = h1; o1.y = l1;
                *(uint2*)(row + pair_off(2 * f4))     = o0;
                *(uint2*)(row + pair_off(2 * f4 + 1)) = o1;
            }
        }
        __syncthreads();

        const uint32_t* ga = sA + (w * 16 + gr) * PGROW;
#pragma unroll
        for (int kc = 0; kc < 4; kc++) {
            const int o0 = kc * 16 + 4 * tg;
            uint4 Aa = *(const uint4*)(ga + o0);
            uint4 Ab = *(const uint4*)(ga + 8 * PGROW + o0);
#pragma unroll
            for (int t8 = 0; t8 < 16; t8++) {
                const uint32_t* f = sB + (t8 * 8 + gr) * PGROW + o0;
                uint4 Bv = *(const uint4*)f;
                mma_f16(acc[t8], Aa.x, Ab.x, Aa.z, Ab.z, Bv.x, Bv.z);
                mma_f16(acc[t8], Aa.x, Ab.x, Aa.z, Ab.z, Bv.y, Bv.w);
                mma_f16(acc[t8], Aa.y, Ab.y, Aa.w, Ab.w, Bv.x, Bv.z);
            }
        }
    }
    __syncthreads();

    if (!modeH) {
        // F staging: rows 36 u32 (hi only); G staging: rows 68 u32 (hi,lo)
        uint32_t* psF = psm;                     // 128*36 = 4608
        uint32_t* psG = psm + 4608;              // 128*68 = 8704
        const int nloc0 = w * 16 + gr;
#pragma unroll
        for (int t8 = 0; t8 < 16; t8++) {
            if (t8 < 8) {
                const int pos = tg * 8 + (t8 >> 1) * 2 + (t8 & 1);
#pragma unroll
                for (int h = 0; h < 2; h++) {
                    uint32_t hi2 = f16x2(acc[t8][2 * h], acc[t8][2 * h + 1]);
                    psF[(nloc0 + h * 8) * 36 + pos] = hi2;
                }
            } else {
                const int off = pair_off((t8 - 8) * 4 + tg);
#pragma unroll
                for (int h = 0; h < 2; h++) {
                    float v0 = acc[t8][2 * h] * LOG2E;
                    float v1 = acc[t8][2 * h + 1] * LOG2E;
                    uint32_t hi2 = f16x2(v0, v1);
                    uint32_t lo2 = f16x2(v0 - f16lo(hi2), v1 - f16hi(hi2));
                    uint2 o; o.x = hi2; o.y = lo2;
                    *(uint2*)(psG + (nloc0 + h * 8) * 68 + off) = o;
                }
            }
        }
        __syncthreads();
#pragma unroll
        for (int i = 0; i < 4; i++) {            // F: 128 rows x 8 uint4
            const int idx = tid + i * 256;
            const int row = idx >> 3, q4 = idx & 7;
            uint4 v = *(const uint4*)(psF + row * 36 + q4 * 4);
            *(uint4*)(g_F + ((size_t)b * N_ + nb0 + row) * 32 + q4 * 4) = v;
        }
#pragma unroll
        for (int i = 0; i < 8; i++) {            // G: 128 rows x 16 uint4
            const int idx = tid + i * 256;
            const int row = idx >> 4, q4 = idx & 15;
            uint4 v = *(const uint4*)(psG + row * 68 + q4 * 4);
            *(uint4*)(g_G + ((size_t)b * N_ + nb0 + row) * 64 + q4 * 4) = v;
        }
    } else {
        const int dloc0 = w * 16 + gr;
#pragma unroll
        for (int nt = 0; nt < 16; nt++) {
            const int Pl = nt * 4 + tg;
            const int qb = Pl & 7;
            const int posl = (Pl & ~15) + ((Pl >> 3) & 1) * 8
                           + (qb & 3) * 2 + (qb >> 2);
            psm[dloc0 * 68 + posl]       = f16x2(acc[nt][0], acc[nt][1]);
            psm[(dloc0 + 8) * 68 + posl] = f16x2(acc[nt][2], acc[nt][3]);
        }
        __syncthreads();
        uint32_t* Hb = (uint32_t*)g_H + (size_t)b * C_ * 2048;
#pragma unroll
        for (int i = 0; i < 8; i++) {
            const int idx = tid + i * 256;
            const int row = idx >> 4, q4 = idx & 15;
            uint4 v = *(const uint4*)(psm + row * 68 + q4 * 4);
            *(uint4*)(Hb + (size_t)((rg - 1) * 128 + row) * 2048
                      + nb0 / 2 + q4 * 4) = v;
        }
    }
}

// ---------------------------------------------------------------------------
// fp16 flash attention. S = 2-pass (Gh.Fh + Gl.Fh) with hi-only tg-major F
// (FROW=36, conflict-free uint4 frag loads spanning all 4 kc).
// PV unchanged (1-pass fp16, LDS.64 frags). 256 thr, 128 q-rows, MT=32.
// ---------------------------------------------------------------------------
#define GROW 80                          // G rows (64 + pad)
#define FROW 36                          // F rows (32 + pad)
#define HROW 24                          // H rows (16 + pad)
#define SG  0
#define SF  (128 * GROW)                 // 10240
#define FPL (MT * FROW)                  // 1152
#define SH  (SF + 2 * FPL)               // 12544
#define HPL (C_ * HROW)                  // 6144
#define SMEMU (SH + 2 * HPL)             // 24832 u32
#define SMEMB (SMEMU * 4)                // 99328 B

__global__ __launch_bounds__(256, 1) void attn_kernel(
    const float* __restrict__ input,
    const float* __restrict__ gamma_p,
    float* __restrict__ out)
{
    extern __shared__ uint32_t sm[];
    uint32_t smu;
    asm("{ .reg .u64 t; cvta.to.shared.u64 t, %1; cvt.u32.u64 %0, t; }"
        : "=r"(smu) : "l"(sm));

    const int tid  = threadIdx.x;
    const int lane = tid & 31;
    const int w    = tid >> 5;
    const int gr   = lane >> 2;
    const int tg   = lane & 3;
    const int n0   = blockIdx.x * 128;
    const int b    = blockIdx.y;

    const uint32_t* FG = g_F + (size_t)b * N_ * 32;
    const uint32_t* HG = (const uint32_t*)(g_H + (size_t)b * C_ * N_);

    {   // stage G tile (128 rows x 64 u32)
        const uint32_t* GG = g_G + ((size_t)b * N_ + n0) * 64;
        for (int i = tid; i < 128 * 16; i += 256) {
            int r = i >> 4, ch = i & 15;
            cp16(smu + (SG + r * GROW + ch * 4) * 4, GG + r * 64 + ch * 4);
        }
    }
    {   // prefetch m-tile 0
        for (int i = tid; i < 256; i += 256) {
            int r = i >> 3, ch = i & 7;
            cp16(smu + (SF + r * FROW + ch * 4) * 4, FG + (size_t)r * 32 + ch * 4);
        }
        for (int i = tid; i < 1024; i += 256) {
            int r = i >> 2, ch = i & 3;
            cp16(smu + (SH + r * HROW + ch * 4) * 4, HG + (size_t)r * 2048 + ch * 4);
        }
        cp_commit();
    }

    float oacc[32][4];
#pragma unroll
    for (int i = 0; i < 32; i++) {
        oacc[i][0] = 0.f; oacc[i][1] = 0.f; oacc[i][2] = 0.f; oacc[i][3] = 0.f;
    }
    const float NEG_INF = __int_as_float(0xff800000);
    float mrow0 = NEG_INF, mrow1 = NEG_INF, lsum0 = 0.f, lsum1 = 0.f;

    const uint32_t* g0 = sm + SG + (w * 16 + gr) * GROW;

#pragma unroll 1
    for (int t = 0; t < N_ / MT; t++) {
        cp_wait0();
        __syncthreads();

        const int cur = t & 1;
        if (t + 1 < N_ / MT) {
            const int m0n = (t + 1) * MT;
            const int nb = cur ^ 1;
            for (int i = tid; i < 256; i += 256) {
                int r = i >> 3, ch = i & 7;
                cp16(smu + (SF + nb * FPL + r * FROW + ch * 4) * 4,
                     FG + (size_t)(m0n + r) * 32 + ch * 4);
            }
            for (int i = tid; i < 1024; i += 256) {
                int r = i >> 2, ch = i & 3;
                cp16(smu + (SH + nb * HPL + r * HROW + ch * 4) * 4,
                     HG + (size_t)r * 2048 + m0n / 2 + ch * 4);
            }
            cp_commit();
        }

        const uint32_t* sFc = sm + SF + cur * FPL;
        const uint32_t* sHc = sm + SH + cur * HPL;

        // ---- S tile: 2-pass fp16 (Gh.Fh + Gl.Fh) ----
        float sc[4][4];
#pragma unroll
        for (int ms = 0; ms < 4; ms++) {
            sc[ms][0] = 0.f; sc[ms][1] = 0.f; sc[ms][2] = 0.f; sc[ms][3] = 0.f;
        }
#pragma unroll
        for (int kh = 0; kh < 2; kh++) {       // kc-pairs (0,1) then (2,3)
            const int o0 = (2 * kh) * 16 + 4 * tg;
            const int o1 = (2 * kh + 1) * 16 + 4 * tg;
            uint4 A0a = *(const uint4*)(g0 + o0);
            uint4 A0b = *(const uint4*)(g0 + 8 * GROW + o0);
            uint4 A1a = *(const uint4*)(g0 + o1);
            uint4 A1b = *(const uint4*)(g0 + 8 * GROW + o1);
#pragma unroll
            for (int ms = 0; ms < 4; ms++) {
                const uint32_t* f = sFc + (ms * 8 + gr) * FROW + tg * 8 + kh * 4;
                uint4 Bv = *(const uint4*)f;   // kc0.b0, kc0.b1, kc1.b0, kc1.b1
                mma_f16(sc[ms], A0a.x, A0b.x, A0a.z, A0b.z, Bv.x, Bv.y);
                mma_f16(sc[ms], A0a.y, A0b.y, A0a.w, A0b.w, Bv.x, Bv.y);
                mma_f16(sc[ms], A1a.x, A1b.x, A1a.z, A1b.z, Bv.z, Bv.w);
                mma_f16(sc[ms], A1a.y, A1b.y, A1a.w, A1b.w, Bv.z, Bv.w);
            }
        }

        // ---- online softmax (log2 domain), lazy O-rescale ----
        float t0 = NEG_INF, t1 = NEG_INF;
#pragma unroll
        for (int ms = 0; ms < 4; ms++) {
            t0 = fmaxf(t0, fmaxf(sc[ms][0], sc[ms][1]));
            t1 = fmaxf(t1, fmaxf(sc[ms][2], sc[ms][3]));
        }
        t0 = fmaxf(t0, __shfl_xor_sync(0xffffffffu, t0, 1));
        t0 = fmaxf(t0, __shfl_xor_sync(0xffffffffu, t0, 2));
        t1 = fmaxf(t1, __shfl_xor_sync(0xffffffffu, t1, 1));
        t1 = fmaxf(t1, __shfl_xor_sync(0xffffffffu, t1, 2));

        const float mn0 = fmaxf(mrow0, t0);
        const float mn1 = fmaxf(mrow1, t1);
        const bool up = (mn0 != mrow0) || (mn1 != mrow1);
        if (__any_sync(0xffffffffu, up)) {
            const float cr0 = ex2(mrow0 - mn0);
            const float cr1 = ex2(mrow1 - mn1);
            lsum0 *= cr0; lsum1 *= cr1;
#pragma unroll
            for (int dt = 0; dt < 32; dt++) {
                oacc[dt][0] *= cr0; oacc[dt][1] *= cr0;
                oacc[dt][2] *= cr1; oacc[dt][3] *= cr1;
            }
            mrow0 = mn0; mrow1 = mn1;
        }
#pragma unroll
        for (int ms = 0; ms < 4; ms++) {
            sc[ms][0] = ex2(sc[ms][0] - mrow0);
            sc[ms][1] = ex2(sc[ms][1] - mrow0);
            sc[ms][2] = ex2(sc[ms][2] - mrow1);
            sc[ms][3] = ex2(sc[ms][3] - mrow1);
            lsum0 += sc[ms][0] + sc[ms][1];
            lsum1 += sc[ms][2] + sc[ms][3];
        }

        // ---- PV: O += P * H, 1-pass fp16; B-frags via LDS.64 (permuted) ----
#pragma unroll
        for (int j = 0; j < 2; j++) {
            const float* cA = sc[2 * j];
            const float* cB = sc[2 * j + 1];
            uint32_t p0 = f16x2(cA[0], cA[1]);
            uint32_t p1 = f16x2(cA[2], cA[3]);
            uint32_t p2 = f16x2(cB[0], cB[1]);
            uint32_t p3 = f16x2(cB[2], cB[3]);
            const uint32_t* hb = sHc + gr * HROW + j * 8 + 2 * tg;
#pragma unroll
            for (int dt = 0; dt < 32; dt++) {
                uint2 bv = *(const uint2*)(hb + dt * 8 * HROW);
                mma_f16(oacc[dt], p0, p1, p2, p3, bv.x, bv.y);
            }
        }
    }

    // ---- epilogue ----
    lsum0 += __shfl_xor_sync(0xffffffffu, lsum0, 1);
    lsum0 += __shfl_xor_sync(0xffffffffu, lsum0, 2);
    lsum1 += __shfl_xor_sync(0xffffffffu, lsum1, 1);
    lsum1 += __shfl_xor_sync(0xffffffffu, lsum1, 2);
    const float inv0 = 1.0f / lsum0;
    const float inv1 = 1.0f / lsum1;
    const float gm = __ldg(gamma_p);

    const int r0 = n0 + w * 16 + gr;
    const int r1 = r0 + 8;
    const size_t base0 = ((size_t)b * N_ + r0) * C_ + tg * 2;
    const size_t base1 = ((size_t)b * N_ + r1) * C_ + tg * 2;
#pragma unroll
    for (int dt = 0; dt < 32; dt++) {
        float2 iv0 = *(const float2*)(input + base0 + dt * 8);
        float2 iv1 = *(const float2*)(input + base1 + dt * 8);
        float2 ov0, ov1;
        ov0.x = fmaf(gm, oacc[dt][0] * inv0, iv0.x);
        ov0.y = fmaf(gm, oacc[dt][1] * inv0, iv0.y);
        ov1.x = fmaf(gm, oacc[dt][2] * inv1, iv1.x);
        ov1.y = fmaf(gm, oacc[dt][3] * inv1, iv1.y);
        *(float2*)(out + base0 + dt * 8) = ov0;
        *(float2*)(out + base1 + dt * 8) = ov1;
    }
}

// ---------------------------------------------------------------------------
extern "C" void kernel_launch(void* const* d_in, const int* in_sizes, int n_in,
                              void* d_out, int out_size) {
    (void)in_sizes; (void)n_in; (void)out_size;
    const float* input = (const float*)d_in[0];
    const float* feat  = (const float*)d_in[1];   // nms_feat
    const float* WF    = (const float*)d_in[2];
    const float* WG    = (const float*)d_in[3];
    const float* WH    = (const float*)d_in[4];
    const float* gamma = (const float*)d_in[5];
    float* out = (float*)d_out;

    cudaFuncSetAttribute(proj_kernel,
                         cudaFuncAttributeMaxDynamicSharedMemorySize, PSMEMB);
    cudaFuncSetAttribute(attn_kernel,
                         cudaFuncAttributeMaxDynamicSharedMemorySize, SMEMB);

    proj_kernel<<<dim3(N_ / 128, 3, B_), 256, PSMEMB>>>(feat, WF, WG, WH);
    attn_kernel<<<dim3(N_ / 128, B_), 256, SMEMB>>>(input, gamma, out);
}

// round 16
// speedup vs baseline: 1.4196x; 1.1334x over previous
#include <cuda_runtime.h>
#include <cuda_fp16.h>
#include <cstdint>

#define B_ 8
#define C_ 256
#define N_ 4096
#define K_ 64
#define MT 64
#define LOG2E 1.4426950408889634f

// g_F: fp16 HI ONLY, tg-major rows of 32 u32: k-pair p (kc=p>>3, qb=p&7,
//      tg=qb&3, slot=qb>>2) stored at position tg*8 + kc*2 + slot.
// g_G: fp16 hi/lo interleaved, permuted rows of 64 u32.
// g_H: fp16 single, transposed [b][d][m-pairs], permuted per 8-pair block.
__device__ uint32_t g_F[(size_t)B_ * N_ * 32];
__device__ uint32_t g_G[(size_t)B_ * N_ * 64];     // pre-scaled by log2(e)
__device__ uint16_t g_H[(size_t)B_ * C_ * N_];

// ---------------- helpers ----------------
__device__ __forceinline__ uint32_t f16x2(float lo, float hi) {
    uint32_t r;
    asm("cvt.rn.f16x2.f32 %0, %1, %2;" : "=r"(r) : "f"(hi), "f"(lo));
    return r;
}
__device__ __forceinline__ float f16lo(uint32_t p) {
    return __half2float(__ushort_as_half((unsigned short)(p & 0xffffu)));
}
__device__ __forceinline__ float f16hi(uint32_t p) {
    return __half2float(__ushort_as_half((unsigned short)(p >> 16)));
}
__device__ __forceinline__ float ex2(float x) {
    float r; asm("ex2.approx.f32 %0, %1;" : "=f"(r) : "f"(x)); return r;
}
__device__ __forceinline__ void mma_f16(float* c,
    uint32_t a0, uint32_t a1, uint32_t a2, uint32_t a3,
    uint32_t b0, uint32_t b1) {
    asm volatile("mma.sync.aligned.m16n8k16.row.col.f32.f16.f16.f32 "
        "{%0,%1,%2,%3},{%4,%5,%6,%7},{%8,%9},{%0,%1,%2,%3};"
        : "+f"(c[0]), "+f"(c[1]), "+f"(c[2]), "+f"(c[3])
        : "r"(a0), "r"(a1), "r"(a2), "r"(a3), "r"(b0), "r"(b1));
}
__device__ __forceinline__ void cp16(uint32_t dst, const void* src) {
    asm volatile("cp.async.cg.shared.global [%0], [%1], 16;" :: "r"(dst), "l"(src));
}
__device__ __forceinline__ void cp_commit() { asm volatile("cp.async.commit_group;"); }
__device__ __forceinline__ void cp_wait0()  { asm volatile("cp.async.wait_group 0;"); }

// G-layout pair permutation: u32 offset of pair p in a 64-u32 row
__device__ __forceinline__ int pair_off(int p) {
    int qb = p & 7;
    return (p >> 3) * 16 + ((qb & 3) * 2 + (qb >> 2)) * 2;
}

// ---------------------------------------------------------------------------
// Tensor-core projection — UNCHANGED from round 14 (106 us, coalesced I/O).
// ---------------------------------------------------------------------------
#define PGROW 80
#define PSMEMB (2 * 128 * PGROW * 4)     // 81920 B

__global__ __launch_bounds__(256, 2) void proj_kernel(
    const float* __restrict__ feat,
    const float* __restrict__ WF,
    const float* __restrict__ WG,
    const float* __restrict__ WH)
{
    extern __shared__ uint32_t psm[];
    uint32_t* sA = psm;
    uint32_t* sB = psm + 128 * PGROW;

    const int tid  = threadIdx.x;
    const int lane = tid & 31;
    const int w    = tid >> 5;
    const int gr   = lane >> 2;
    const int tg   = lane & 3;
    const int nb0  = blockIdx.x * 128;
    const int rg   = blockIdx.y;
    const int b    = blockIdx.z;
    const bool modeH = (rg > 0);
    const float* fb = feat + (size_t)b * C_ * N_;

    float acc[16][4];
#pragma unroll
    for (int i = 0; i < 16; i++) {
        acc[i][0] = 0.f; acc[i][1] = 0.f; acc[i][2] = 0.f; acc[i][3] = 0.f;
    }

#pragma unroll 1
    for (int kt = 0; kt < 4; kt++) {
        const int c0 = kt * 64;
        __syncthreads();

        {   // stage feat tile (coalesced over n)
            uint32_t* dst = modeH ? sB : sA;
            const int n_i  = tid & 127;
            const int half = tid >> 7;
            uint32_t* row = dst + n_i * PGROW;
            const float* fp = fb + (size_t)(c0 + half * 32) * N_ + nb0 + n_i;
#pragma unroll
            for (int p = 0; p < 16; p++) {
                float x0 = fp[(size_t)(2 * p) * N_];
                float x1 = fp[(size_t)(2 * p + 1) * N_];
                uint32_t hi2 = f16x2(x0, x1);
                uint32_t lo2 = f16x2(x0 - f16lo(hi2), x1 - f16hi(hi2));
                uint2 o; o.x = hi2; o.y = lo2;
                *(uint2*)(row + pair_off(half * 16 + p)) = o;
            }
        }
        {   // stage W tile (linear float4)
            uint32_t* dst = modeH ? sA : sB;
#pragma unroll
            for (int i = 0; i < 8; i++) {
                const int idx = tid + i * 256;
                const int r = idx >> 4, f4 = idx & 15;
                const float* Wr;
                if (modeH) Wr = WH + (size_t)((rg - 1) * 128 + r) * C_;
                else       Wr = (r < 64) ? WF + (size_t)r * C_
                                         : WG + (size_t)(r - 64) * C_;
                float4 x = __ldg((const float4*)(Wr + c0 + f4 * 4));
                uint32_t h0 = f16x2(x.x, x.y);
                uint32_t l0 = f16x2(x.x - f16lo(h0), x.y - f16hi(h0));
                uint32_t h1 = f16x2(x.z, x.w);
                uint32_t l1 = f16x2(x.z - f16lo(h1), x.w - f16hi(h1));
                uint32_t* row = dst + r * PGROW;
                uint2 o0; o0.x = h0; o0.y = l0;
                uint2 o1; o1.x = h1; o1.y = l1;
                *(uint2*)(row + pair_off(2 * f4))     = o0;
                *(uint2*)(row + pair_off(2 * f4 + 1)) = o1;
            }
        }
        __syncthreads();

        const uint32_t* ga = sA + (w * 16 + gr) * PGROW;
#pragma unroll
        for (int kc = 0; kc < 4; kc++) {
            const int o0 = kc * 16 + 4 * tg;
            uint4 Aa = *(const uint4*)(ga + o0);
            uint4 Ab = *(const uint4*)(ga + 8 * PGROW + o0);
#pragma unroll
            for (int t8 = 0; t8 < 16; t8++) {
                const uint32_t* f = sB + (t8 * 8 + gr) * PGROW + o0;
                uint4 Bv = *(const uint4*)f;
                mma_f16(acc[t8], Aa.x, Ab.x, Aa.z, Ab.z, Bv.x, Bv.z);
                mma_f16(acc[t8], Aa.x, Ab.x, Aa.z, Ab.z, Bv.y, Bv.w);
                mma_f16(acc[t8], Aa.y, Ab.y, Aa.w, Ab.w, Bv.x, Bv.z);
            }
        }
    }
    __syncthreads();

    if (!modeH) {
        uint32_t* psF = psm;                     // 128*36
        uint32_t* psG = psm + 4608;              // 128*68
        const int nloc0 = w * 16 + gr;
#pragma unroll
        for (int t8 = 0; t8 < 16; t8++) {
            if (t8 < 8) {
                const int pos = tg * 8 + (t8 >> 1) * 2 + (t8 & 1);
#pragma unroll
                for (int h = 0; h < 2; h++) {
                    uint32_t hi2 = f16x2(acc[t8][2 * h], acc[t8][2 * h + 1]);
                    psF[(nloc0 + h * 8) * 36 + pos] = hi2;
                }
            } else {
                const int off = pair_off((t8 - 8) * 4 + tg);
#pragma unroll
                for (int h = 0; h < 2; h++) {
                    float v0 = acc[t8][2 * h] * LOG2E;
                    float v1 = acc[t8][2 * h + 1] * LOG2E;
                    uint32_t hi2 = f16x2(v0, v1);
                    uint32_t lo2 = f16x2(v0 - f16lo(hi2), v1 - f16hi(hi2));
                    uint2 o; o.x = hi2; o.y = lo2;
                    *(uint2*)(psG + (nloc0 + h * 8) * 68 + off) = o;
                }
            }
        }
        __syncthreads();
#pragma unroll
        for (int i = 0; i < 4; i++) {
            const int idx = tid + i * 256;
            const int row = idx >> 3, q4 = idx & 7;
            uint4 v = *(const uint4*)(psF + row * 36 + q4 * 4);
            *(uint4*)(g_F + ((size_t)b * N_ + nb0 + row) * 32 + q4 * 4) = v;
        }
#pragma unroll
        for (int i = 0; i < 8; i++) {
            const int idx = tid + i * 256;
            const int row = idx >> 4, q4 = idx & 15;
            uint4 v = *(const uint4*)(psG + row * 68 + q4 * 4);
            *(uint4*)(g_G + ((size_t)b * N_ + nb0 + row) * 64 + q4 * 4) = v;
        }
    } else {
        const int dloc0 = w * 16 + gr;
#pragma unroll
        for (int nt = 0; nt < 16; nt++) {
            const int Pl = nt * 4 + tg;
            const int qb = Pl & 7;
            const int posl = (Pl & ~15) + ((Pl >> 3) & 1) * 8
                           + (qb & 3) * 2 + (qb >> 2);
            psm[dloc0 * 68 + posl]       = f16x2(acc[nt][0], acc[nt][1]);
            psm[(dloc0 + 8) * 68 + posl] = f16x2(acc[nt][2], acc[nt][3]);
        }
        __syncthreads();
        uint32_t* Hb = (uint32_t*)g_H + (size_t)b * C_ * 2048;
#pragma unroll
        for (int i = 0; i < 8; i++) {
            const int idx = tid + i * 256;
            const int row = idx >> 4, q4 = idx & 15;
            uint4 v = *(const uint4*)(psm + row * 68 + q4 * 4);
            *(uint4*)(Hb + (size_t)((rg - 1) * 128 + row) * 2048
                      + nb0 / 2 + q4 * 4) = v;
        }
    }
}

// ---------------------------------------------------------------------------
// fp16 flash attention, MT=64: halved per-tile barrier/softmax overhead.
// S = 2-pass (Gh+Gl).Fh over 64 m (64 HMMA burst); softmax 32 vals/thread;
// PV 1-pass fp16 k=64 (128 HMMA burst). 256 thr, 128 q-rows, 64 iterations.
// ---------------------------------------------------------------------------
#define GROW 80                          // G rows (64 + pad)
#define FROW 36                          // F rows (32 + pad)
#define HROW 40                          // H rows (32 + 8 pad)
#define SG  0
#define SF  (128 * GROW)                 // 10240
#define FPL (MT * FROW)                  // 2304
#define SH  (SF + 2 * FPL)               // 14848
#define HPL (C_ * HROW)                  // 10240
#define SMEMU (SH + 2 * HPL)             // 35328 u32
#define SMEMB (SMEMU * 4)                // 141312 B

__global__ __launch_bounds__(256, 1) void attn_kernel(
    const float* __restrict__ input,
    const float* __restrict__ gamma_p,
    float* __restrict__ out)
{
    extern __shared__ uint32_t sm[];
    uint32_t smu;
    asm("{ .reg .u64 t; cvta.to.shared.u64 t, %1; cvt.u32.u64 %0, t; }"
        : "=r"(smu) : "l"(sm));

    const int tid  = threadIdx.x;
    const int lane = tid & 31;
    const int w    = tid >> 5;
    const int gr   = lane >> 2;
    const int tg   = lane & 3;
    const int n0   = blockIdx.x * 128;
    const int b    = blockIdx.y;

    const uint32_t* FG = g_F + (size_t)b * N_ * 32;
    const uint32_t* HG = (const uint32_t*)(g_H + (size_t)b * C_ * N_);

    {   // stage G tile (128 rows x 64 u32)
        const uint32_t* GG = g_G + ((size_t)b * N_ + n0) * 64;
        for (int i = tid; i < 128 * 16; i += 256) {
            int r = i >> 4, ch = i & 15;
            cp16(smu + (SG + r * GROW + ch * 4) * 4, GG + r * 64 + ch * 4);
        }
    }
    {   // prefetch m-tile 0: F 64 rows x 8 chunks, H 256 rows x 8 chunks
        for (int i = tid; i < 512; i += 256) {
            int r = i >> 3, ch = i & 7;
            cp16(smu + (SF + r * FROW + ch * 4) * 4, FG + (size_t)r * 32 + ch * 4);
        }
        for (int i = tid; i < 2048; i += 256) {
            int r = i >> 3, ch = i & 7;
            cp16(smu + (SH + r * HROW + ch * 4) * 4, HG + (size_t)r * 2048 + ch * 4);
        }
        cp_commit();
    }

    float oacc[32][4];
#pragma unroll
    for (int i = 0; i < 32; i++) {
        oacc[i][0] = 0.f; oacc[i][1] = 0.f; oacc[i][2] = 0.f; oacc[i][3] = 0.f;
    }
    const float NEG_INF = __int_as_float(0xff800000);
    float mrow0 = NEG_INF, mrow1 = NEG_INF, lsum0 = 0.f, lsum1 = 0.f;

    const uint32_t* g0 = sm + SG + (w * 16 + gr) * GROW;

#pragma unroll 1
    for (int t = 0; t < N_ / MT; t++) {
        cp_wait0();
        __syncthreads();

        const int cur = t & 1;
        if (t + 1 < N_ / MT) {
            const int m0n = (t + 1) * MT;
            const int nb = cur ^ 1;
            for (int i = tid; i < 512; i += 256) {
                int r = i >> 3, ch = i & 7;
                cp16(smu + (SF + nb * FPL + r * FROW + ch * 4) * 4,
                     FG + (size_t)(m0n + r) * 32 + ch * 4);
            }
            for (int i = tid; i < 2048; i += 256) {
                int r = i >> 3, ch = i & 7;
                cp16(smu + (SH + nb * HPL + r * HROW + ch * 4) * 4,
                     HG + (size_t)r * 2048 + m0n / 2 + ch * 4);
            }
            cp_commit();
        }

        const uint32_t* sFc = sm + SF + cur * FPL;
        const uint32_t* sHc = sm + SH + cur * HPL;

        // ---- S tile: 2-pass fp16 (Gh.Fh + Gl.Fh), 64 m-rows ----
        float sc[8][4];
#pragma unroll
        for (int ms = 0; ms < 8; ms++) {
            sc[ms][0] = 0.f; sc[ms][1] = 0.f; sc[ms][2] = 0.f; sc[ms][3] = 0.f;
        }
#pragma unroll
        for (int kh = 0; kh < 2; kh++) {       // kc-pairs (0,1) then (2,3)
            const int o0 = (2 * kh) * 16 + 4 * tg;
            const int o1 = (2 * kh + 1) * 16 + 4 * tg;
            uint4 A0a = *(const uint4*)(g0 + o0);
            uint4 A0b = *(const uint4*)(g0 + 8 * GROW + o0);
            uint4 A1a = *(const uint4*)(g0 + o1);
            uint4 A1b = *(const uint4*)(g0 + 8 * GROW + o1);
#pragma unroll
            for (int ms = 0; ms < 8; ms++) {
                const uint32_t* f = sFc + (ms * 8 + gr) * FROW + tg * 8 + kh * 4;
                uint4 Bv = *(const uint4*)f;
                mma_f16(sc[ms], A0a.x, A0b.x, A0a.z, A0b.z, Bv.x, Bv.y);
                mma_f16(sc[ms], A0a.y, A0b.y, A0a.w, A0b.w, Bv.x, Bv.y);
                mma_f16(sc[ms], A1a.x, A1b.x, A1a.z, A1b.z, Bv.z, Bv.w);
                mma_f16(sc[ms], A1a.y, A1b.y, A1a.w, A1b.w, Bv.z, Bv.w);
            }
        }

        // ---- online softmax (log2 domain), lazy O-rescale ----
        float t0 = NEG_INF, t1 = NEG_INF;
#pragma unroll
        for (int ms = 0; ms < 8; ms++) {
            t0 = fmaxf(t0, fmaxf(sc[ms][0], sc[ms][1]));
            t1 = fmaxf(t1, fmaxf(sc[ms][2], sc[ms][3]));
        }
        t0 = fmaxf(t0, __shfl_xor_sync(0xffffffffu, t0, 1));
        t0 = fmaxf(t0, __shfl_xor_sync(0xffffffffu, t0, 2));
        t1 = fmaxf(t1, __shfl_xor_sync(0xffffffffu, t1, 1));
        t1 = fmaxf(t1, __shfl_xor_sync(0xffffffffu, t1, 2));

        const float mn0 = fmaxf(mrow0, t0);
        const float mn1 = fmaxf(mrow1, t1);
        const bool up = (mn0 != mrow0) || (mn1 != mrow1);
        if (__any_sync(0xffffffffu, up)) {
            const float cr0 = ex2(mrow0 - mn0);
            const float cr1 = ex2(mrow1 - mn1);
            lsum0 *= cr0; lsum1 *= cr1;
#pragma unroll
            for (int dt = 0; dt < 32; dt++) {
                oacc[dt][0] *= cr0; oacc[dt][1] *= cr0;
                oacc[dt][2] *= cr1; oacc[dt][3] *= cr1;
            }
            mrow0 = mn0; mrow1 = mn1;
        }
#pragma unroll
        for (int ms = 0; ms < 8; ms++) {
            sc[ms][0] = ex2(sc[ms][0] - mrow0);
            sc[ms][1] = ex2(sc[ms][1] - mrow0);
            sc[ms][2] = ex2(sc[ms][2] - mrow1);
            sc[ms][3] = ex2(sc[ms][3] - mrow1);
            lsum0 += sc[ms][0] + sc[ms][1];
            lsum1 += sc[ms][2] + sc[ms][3];
        }

        // ---- PV: O += P * H, 1-pass fp16 over k=64; B-frags LDS.64 ----
#pragma unroll
        for (int j = 0; j < 4; j++) {
            const float* cA = sc[2 * j];
            const float* cB = sc[2 * j + 1];
            uint32_t p0 = f16x2(cA[0], cA[1]);
            uint32_t p1 = f16x2(cA[2], cA[3]);
            uint32_t p2 = f16x2(cB[0], cB[1]);
            uint32_t p3 = f16x2(cB[2], cB[3]);
            const uint32_t* hb = sHc + gr * HROW + j * 8 + 2 * tg;
#pragma unroll
            for (int dt = 0; dt < 32; dt++) {
                uint2 bv = *(const uint2*)(hb + dt * 8 * HROW);
                mma_f16(oacc[dt], p0, p1, p2, p3, bv.x, bv.y);
            }
        }
    }

    // ---- epilogue ----
    lsum0 += __shfl_xor_sync(0xffffffffu, lsum0, 1);
    lsum0 += __shfl_xor_sync(0xffffffffu, lsum0, 2);
    lsum1 += __shfl_xor_sync(0xffffffffu, lsum1, 1);
    lsum1 += __shfl_xor_sync(0xffffffffu, lsum1, 2);
    const float inv0 = 1.0f / lsum0;
    const float inv1 = 1.0f / lsum1;
    const float gm = __ldg(gamma_p);

    const int r0 = n0 + w * 16 + gr;
    const int r1 = r0 + 8;
    const size_t base0 = ((size_t)b * N_ + r0) * C_ + tg * 2;
    const size_t base1 = ((size_t)b * N_ + r1) * C_ + tg * 2;
#pragma unroll
    for (int dt = 0; dt < 32; dt++) {
        float2 iv0 = *(const float2*)(input + base0 + dt * 8);
        float2 iv1 = *(const float2*)(input + base1 + dt * 8);
        float2 ov0, ov1;
        ov0.x = fmaf(gm, oacc[dt][0] * inv0, iv0.x);
        ov0.y = fmaf(gm, oacc[dt][1] * inv0, iv0.y);
        ov1.x = fmaf(gm, oacc[dt][2] * inv1, iv1.x);
        ov1.y = fmaf(gm, oacc[dt][3] * inv1, iv1.y);
        *(float2*)(out + base0 + dt * 8) = ov0;
        *(float2*)(out + base1 + dt * 8) = ov1;
    }
}

// ---------------------------------------------------------------------------
extern "C" void kernel_launch(void* const* d_in, const int* in_sizes, int n_in,
                              void* d_out, int out_size) {
    (void)in_sizes; (void)n_in; (void)out_size;
    const float* input = (const float*)d_in[0];
    const float* feat  = (const float*)d_in[1];   // nms_feat
    const float* WF    = (const float*)d_in[2];
    const float* WG    = (const float*)d_in[3];
    const float* WH    = (const float*)d_in[4];
    const float* gamma = (const float*)d_in[5];
    float* out = (float*)d_out;

    cudaFuncSetAttribute(proj_kernel,
                         cudaFuncAttributeMaxDynamicSharedMemorySize, PSMEMB);
    cudaFuncSetAttribute(attn_kernel,
                         cudaFuncAttributeMaxDynamicSharedMemorySize, SMEMB);

    proj_kernel<<<dim3(N_ / 128, 3, B_), 256, PSMEMB>>>(feat, WF, WG, WH);
    attn_kernel<<<dim3(N_ / 128, B_), 256, SMEMB>>>(input, gamma, out);
}